// round 1
// baseline (speedup 1.0000x reference)
#include <cuda_runtime.h>
#include <cuda_bf16.h>
#include <cstddef>

// ---------------- scratch (device globals; no allocation allowed) ----------
__device__ float g_bufA[33554432];   // y ping (max: L1 out 128*64*64*64)
__device__ float g_bufB[16777216];   // y pong (max: L2 out 128*128*32*32)
__device__ float g_dw[8388608];      // dwconv out (max: L2 in 128*64*32*32)
__device__ float g_kern[524288];     // dynamic kernels (max: L4 128*256*16)
__device__ float g_sums[1024];       // per-channel sum / sumsq
__device__ float g_ss[1024];         // per-channel scale / shift

// ---------------- dynamic kernel: tanh(e @ W + b) ---------------------------
__global__ void dynk_kernel(const int* __restrict__ label, const float* __restrict__ emb,
                            const float* __restrict__ W, const float* __restrict__ bias,
                            float* __restrict__ out, int CK)
{
    int i = blockIdx.x * blockDim.x + threadIdx.x;
    int b = blockIdx.y;
    if (i >= CK) return;
    const float* e = emb + label[b] * 5;
    float a = bias[i];
#pragma unroll
    for (int t = 0; t < 5; t++) a += e[t] * W[t * CK + i];
    out[(size_t)b * CK + i] = tanhf(a);
}

// ---------------- layer-1 depthwise conv (NCHW input -> NHWC out, C=3) ------
__global__ void dwconv1_kernel(const float* __restrict__ x, const float* __restrict__ kern,
                               float* __restrict__ out)
{
    int b = blockIdx.y;
    int px = blockIdx.x * blockDim.x + threadIdx.x;   // 0..4095
    if (px >= 64 * 64) return;
    int oh = px >> 6, ow = px & 63;
#pragma unroll
    for (int c = 0; c < 3; c++) {
        const float* xp = x + ((size_t)b * 3 + c) * 128 * 128;
        const float* kb = kern + ((size_t)b * 3 + c) * 16;
        float a = 0.f;
#pragma unroll
        for (int kh = 0; kh < 4; kh++) {
            int ih = oh * 2 - 1 + kh;
            if ((unsigned)ih >= 128u) continue;
#pragma unroll
            for (int kw = 0; kw < 4; kw++) {
                int iw = ow * 2 - 1 + kw;
                if ((unsigned)iw >= 128u) continue;
                a += xp[ih * 128 + iw] * kb[kh * 4 + kw];
            }
        }
        out[((size_t)b * 4096 + px) * 3 + c] = a;
    }
}

// ---------------- generic depthwise conv (NHWC, BN affine applied on load) --
__global__ void dwconv_kernel(const float* __restrict__ Yin, const float* __restrict__ ss,
                              const float* __restrict__ kern, float* __restrict__ out,
                              int C, int Ct, int cpb, int Hin, int Win, int Hout, int Wout,
                              int ksz, int stride, int pad)
{
    int b  = blockIdx.y;
    int px = blockIdx.x * cpb + threadIdx.x / Ct;
    int c0 = threadIdx.x % Ct;
    if (threadIdx.x >= Ct * cpb) return;
    if (px >= Hout * Wout) return;
    int oh = px / Wout, ow = px % Wout;
    for (int c = c0; c < C; c += Ct) {
        float sc = ss[c], sh = ss[C + c];
        const float* kb = kern + ((size_t)b * C + c) * ksz * ksz;
        float a = 0.f;
        for (int kh = 0; kh < ksz; kh++) {
            int ih = oh * stride - pad + kh;
            if ((unsigned)ih >= (unsigned)Hin) continue;
            for (int kw = 0; kw < ksz; kw++) {
                int iw = ow * stride - pad + kw;
                if ((unsigned)iw >= (unsigned)Win) continue;
                float v = Yin[(((size_t)b * Hin + ih) * Win + iw) * C + c];
                a += (v * sc + sh) * kb[kh * ksz + kw];
            }
        }
        out[(((size_t)b * Hout + oh) * Wout + ow) * C + c] = a;
    }
}

// ---------------- channel mixer GEMM + lrelu (+stats) / sigmoid -------------
// X: M x K row-major (NHWC rows), Wt: K x N, Y: M x N (mode 0) or NCHW (mode 1)
#define BM 64
#define BN 64
#define BKK 8
__global__ void mix_gemm_kernel(const float* __restrict__ X, const float* __restrict__ Wt,
                                const float* __restrict__ bias, float* __restrict__ Y,
                                float* __restrict__ sums,
                                int M, int N, int K, int mode, int spatial)
{
    __shared__ float As[BKK][BM];
    __shared__ float Bs[BKK][BN];
    __shared__ float sSum[BN], sSq[BN];

    int tid = threadIdx.x;
    int tx = tid & 15, ty = tid >> 4;
    int m0 = blockIdx.x * BM;
    int n0 = blockIdx.y * BN;

    if (mode == 0 && tid < BN) { sSum[tid] = 0.f; sSq[tid] = 0.f; }

    float acc[4][4];
#pragma unroll
    for (int i = 0; i < 4; i++)
#pragma unroll
        for (int j = 0; j < 4; j++) acc[i][j] = 0.f;

    for (int k0 = 0; k0 < K; k0 += BKK) {
        for (int e = tid; e < BM * BKK; e += 256) {
            int m = e >> 3, k = e & 7;
            As[k][m] = (k0 + k < K) ? X[(size_t)(m0 + m) * K + k0 + k] : 0.f;
        }
        for (int e = tid; e < BN * BKK; e += 256) {
            int k = e >> 6, n = e & 63;
            Bs[k][n] = (k0 + k < K) ? Wt[(size_t)(k0 + k) * N + n0 + n] : 0.f;
        }
        __syncthreads();
#pragma unroll
        for (int kk = 0; kk < BKK; kk++) {
            float a[4], bb[4];
#pragma unroll
            for (int i = 0; i < 4; i++) a[i] = As[kk][ty * 4 + i];
#pragma unroll
            for (int j = 0; j < 4; j++) bb[j] = Bs[kk][tx * 4 + j];
#pragma unroll
            for (int i = 0; i < 4; i++)
#pragma unroll
                for (int j = 0; j < 4; j++) acc[i][j] += a[i] * bb[j];
        }
        __syncthreads();
    }

    if (mode == 0) {
        float csum[4] = {0.f, 0.f, 0.f, 0.f};
        float csq[4]  = {0.f, 0.f, 0.f, 0.f};
#pragma unroll
        for (int i = 0; i < 4; i++) {
            int m = m0 + ty * 4 + i;
#pragma unroll
            for (int j = 0; j < 4; j++) {
                int n = n0 + tx * 4 + j;
                float v = acc[i][j] + bias[n];
                v = v > 0.f ? v : 0.2f * v;          // leaky relu 0.2
                Y[(size_t)m * N + n] = v;
                csum[j] += v; csq[j] += v * v;
            }
        }
#pragma unroll
        for (int j = 0; j < 4; j++) {
            atomicAdd(&sSum[tx * 4 + j], csum[j]);
            atomicAdd(&sSq[tx * 4 + j], csq[j]);
        }
        __syncthreads();
        if (tid < BN) {
            atomicAdd(&sums[n0 + tid],     sSum[tid]);
            atomicAdd(&sums[N + n0 + tid], sSq[tid]);
        }
    } else {
#pragma unroll
        for (int i = 0; i < 4; i++) {
            int m = m0 + ty * 4 + i;
            int b = m / spatial, p = m % spatial;
#pragma unroll
            for (int j = 0; j < 4; j++) {
                int n = n0 + tx * 4 + j;
                float v = acc[i][j] + bias[n];
                v = 1.f / (1.f + expf(-v));           // sigmoid
                Y[((size_t)b * N + n) * spatial + p] = v;
            }
        }
    }
}

// ---------------- BN helpers -------------------------------------------------
__global__ void zero_kernel(float* p, int n)
{
    int i = blockIdx.x * blockDim.x + threadIdx.x;
    if (i < n) p[i] = 0.f;
}

__global__ void bn_final_kernel(const float* __restrict__ sums,
                                const float* __restrict__ g, const float* __restrict__ b,
                                float* __restrict__ ss, int C, float invCnt)
{
    int c = blockIdx.x * blockDim.x + threadIdx.x;
    if (c >= C) return;
    float mean = sums[c] * invCnt;
    float var  = sums[C + c] * invCnt - mean * mean;
    float sc = g[c] * rsqrtf(var + 1e-5f);
    ss[c] = sc;
    ss[C + c] = b[c] - mean * sc;
}

__global__ void write_label_kernel(const int* __restrict__ label, float* __restrict__ out, int n)
{
    int i = threadIdx.x;
    if (i < n) out[i] = (float)label[i];
}

// ---------------- launcher ---------------------------------------------------
extern "C" void kernel_launch(void* const* d_in, const int* in_sizes, int n_in,
                              void* d_out, int out_size)
{
    const float* input = (const float*)d_in[0];
    const int*   label = (const int*)d_in[1];
    const float* emb   = (const float*)d_in[2];
    const float* lw[5] = {(const float*)d_in[3], (const float*)d_in[5], (const float*)d_in[7],
                          (const float*)d_in[9], (const float*)d_in[11]};
    const float* lb[5] = {(const float*)d_in[4], (const float*)d_in[6], (const float*)d_in[8],
                          (const float*)d_in[10], (const float*)d_in[12]};
    const float* cmw[5] = {(const float*)d_in[13], (const float*)d_in[15], (const float*)d_in[17],
                           (const float*)d_in[19], (const float*)d_in[21]};
    const float* cmb[5] = {(const float*)d_in[14], (const float*)d_in[16], (const float*)d_in[18],
                           (const float*)d_in[20], (const float*)d_in[22]};
    const float* bng[4] = {(const float*)d_in[23], (const float*)d_in[25],
                           (const float*)d_in[27], (const float*)d_in[29]};
    const float* bnb[4] = {(const float*)d_in[24], (const float*)d_in[26],
                           (const float*)d_in[28], (const float*)d_in[30]};

    float *pA, *pB, *pDw, *pK, *pSums, *pSS;
    cudaGetSymbolAddress((void**)&pA,    g_bufA);
    cudaGetSymbolAddress((void**)&pB,    g_bufB);
    cudaGetSymbolAddress((void**)&pDw,   g_dw);
    cudaGetSymbolAddress((void**)&pK,    g_kern);
    cudaGetSymbolAddress((void**)&pSums, g_sums);
    cudaGetSymbolAddress((void**)&pSS,   g_ss);

    float* out = (float*)d_out;

    // ---------- Layer 1: dwconv(3ch,128->64) + mix(3->64) + bn1 ----------
    {
        int CK = 3 * 16;
        dynk_kernel<<<dim3((CK + 255) / 256, 128), 256>>>(label, emb, lw[0], lb[0], pK, CK);
        dwconv1_kernel<<<dim3(16, 128), 256>>>(input, pK, pDw);
        zero_kernel<<<1, 128>>>(pSums, 128);
        int M = 128 * 64 * 64, N = 64, K = 3;
        mix_gemm_kernel<<<dim3(M / BM, N / BN), 256>>>(pDw, cmw[0], cmb[0], pA, pSums, M, N, K, 0, 0);
        bn_final_kernel<<<1, 64>>>(pSums, bng[0], bnb[0], pSS, 64, 1.f / (float)M);
    }
    // ---------- Layer 2: dwconv(64ch,64->32,k4) + mix(64->128) + bn2 ----------
    {
        int CK = 64 * 16;
        dynk_kernel<<<dim3((CK + 255) / 256, 128), 256>>>(label, emb, lw[1], lb[1], pK, CK);
        dwconv_kernel<<<dim3(1024 / 4, 128), 256>>>(pA, pSS, pK, pDw,
                                                    64, 64, 4, 64, 64, 32, 32, 4, 2, 1);
        zero_kernel<<<1, 256>>>(pSums, 256);
        int M = 128 * 32 * 32, N = 128, K = 64;
        mix_gemm_kernel<<<dim3(M / BM, N / BN), 256>>>(pDw, cmw[1], cmb[1], pB, pSums, M, N, K, 0, 0);
        bn_final_kernel<<<1, 128>>>(pSums, bng[1], bnb[1], pSS, 128, 1.f / (float)M);
    }
    // ---------- Layer 3: dwconv(128ch,32->16,k3) + mix(128->256) + bn3 ----------
    {
        int CK = 128 * 9;
        dynk_kernel<<<dim3((CK + 255) / 256, 128), 256>>>(label, emb, lw[2], lb[2], pK, CK);
        dwconv_kernel<<<dim3(256 / 2, 128), 256>>>(pB, pSS, pK, pDw,
                                                   128, 128, 2, 32, 32, 16, 16, 3, 2, 1);
        zero_kernel<<<1, 512>>>(pSums, 512);
        int M = 128 * 16 * 16, N = 256, K = 128;
        mix_gemm_kernel<<<dim3(M / BM, N / BN), 256>>>(pDw, cmw[2], cmb[2], pA, pSums, M, N, K, 0, 0);
        bn_final_kernel<<<1, 256>>>(pSums, bng[2], bnb[2], pSS, 256, 1.f / (float)M);
    }
    // ---------- Layer 4: dwconv(256ch,16->8,k4) + mix(256->512) + bn4 ----------
    {
        int CK = 256 * 16;
        dynk_kernel<<<dim3((CK + 255) / 256, 128), 256>>>(label, emb, lw[3], lb[3], pK, CK);
        dwconv_kernel<<<dim3(64, 128), 256>>>(pA, pSS, pK, pDw,
                                              256, 256, 1, 16, 16, 8, 8, 4, 2, 1);
        zero_kernel<<<1, 1024>>>(pSums, 1024);
        int M = 128 * 8 * 8, N = 512, K = 256;
        mix_gemm_kernel<<<dim3(M / BM, N / BN), 256>>>(pDw, cmw[3], cmb[3], pB, pSums, M, N, K, 0, 0);
        bn_final_kernel<<<1, 512>>>(pSums, bng[3], bnb[3], pSS, 512, 1.f / (float)M);
    }
    // ---------- Layer 5: dwconv(512ch,8->7,k2,s1,p0) + mix(512->512) + sigmoid -> d_out (NCHW)
    {
        int CK = 512 * 4;
        dynk_kernel<<<dim3((CK + 255) / 256, 128), 256>>>(label, emb, lw[4], lb[4], pK, CK);
        dwconv_kernel<<<dim3(49, 128), 256>>>(pB, pSS, pK, pDw,
                                              512, 256, 1, 8, 8, 7, 7, 2, 1, 0);
        int M = 128 * 49, N = 512, K = 512;
        mix_gemm_kernel<<<dim3(M / BM, N / BN), 256>>>(pDw, cmw[4], cmb[4], out, nullptr, M, N, K, 1, 49);
    }
    // ---------- label tail (if output concatenates (z, label)) ----------
    {
        long long zElems = 128LL * 512 * 49;
        long long tail = (long long)out_size - zElems;
        if (tail > 0) {
            int n = tail > 128 ? 128 : (int)tail;
            write_label_kernel<<<1, 128>>>(label, out + zElems, n);
        }
    }
}

// round 2
// speedup vs baseline: 1.2930x; 1.2930x over previous
#include <cuda_runtime.h>
#include <cuda_bf16.h>
#include <cstddef>

typedef unsigned long long ull;

// ---------------- scratch (device globals; no allocation allowed) ----------
__device__ float g_bufA[33554432];   // ping (max: L1 out 128*64*64*64)
__device__ float g_bufB[16777216];   // pong (max: L2 out 128*128*32*32)
__device__ float g_dw[8388608];      // dwconv out (max: L2 in 128*64*32*32)
__device__ float g_kern[524288];     // dynamic kernels (max: L4 128*256*16)
__device__ float g_sums[1024];       // per-channel sum / sumsq
__device__ float g_ss[1024];         // per-channel scale / shift

// ---------------- f32x2 helpers (sm_103a packed fp32 pipe) ------------------
__device__ __forceinline__ ull pack2(float lo, float hi) {
    ull r; asm("mov.b64 %0, {%1, %2};" : "=l"(r) : "f"(lo), "f"(hi)); return r;
}
__device__ __forceinline__ ull dup2(float v) {
    ull r; asm("mov.b64 %0, {%1, %1};" : "=l"(r) : "f"(v)); return r;
}
__device__ __forceinline__ void fma2(ull& d, ull a, ull b) {
    asm("fma.rn.f32x2 %0, %1, %2, %0;" : "+l"(d) : "l"(a), "l"(b));
}
__device__ __forceinline__ float2 unpack2(ull v) {
    float2 f; asm("mov.b64 {%0, %1}, %2;" : "=f"(f.x), "=f"(f.y) : "l"(v)); return f;
}

// ---------------- dynamic kernel: tanh(e @ W + b) ---------------------------
__global__ void dynk_kernel(const int* __restrict__ label, const float* __restrict__ emb,
                            const float* __restrict__ W, const float* __restrict__ bias,
                            float* __restrict__ out, int CK)
{
    int i = blockIdx.x * blockDim.x + threadIdx.x;
    int b = blockIdx.y;
    if (i >= CK) return;
    const float* e = emb + label[b] * 5;
    float a = bias[i];
#pragma unroll
    for (int t = 0; t < 5; t++) a += e[t] * W[t * CK + i];
    out[(size_t)b * CK + i] = tanhf(a);
}

// ---------------- layer 1 fused: dwconv(3ch) + mix(3->64) + lrelu + stats ---
__global__ __launch_bounds__(256) void l1_fused_kernel(
    const float* __restrict__ x, const float* __restrict__ kern,
    const float* __restrict__ W, const float* __restrict__ bias,
    float* __restrict__ Y, float* __restrict__ sums)
{
    __shared__ float sW[3][64];
    __shared__ float sB[64];
    __shared__ float sK[3][16];
    __shared__ float sD[3][64];
    __shared__ float sSum[64], sSq[64];

    int b = blockIdx.y, oh = blockIdx.x;
    int tid = threadIdx.x;

    if (tid < 192) sW[tid / 64][tid % 64] = W[tid];              // W: 3x64 row-major
    if (tid < 64) { sB[tid] = bias[tid]; sSum[tid] = 0.f; sSq[tid] = 0.f; }
    if (tid >= 192 && tid < 240) { int q = tid - 192; sK[q / 16][q % 16] = kern[(size_t)b * 48 + q]; }
    __syncthreads();

    if (tid < 192) {
        int c = tid / 64, ow = tid % 64;
        const float* xp = x + ((size_t)b * 3 + c) * 16384;
        float a = 0.f;
#pragma unroll
        for (int kh = 0; kh < 4; kh++) {
            int ih = oh * 2 - 1 + kh;
            if ((unsigned)ih < 128u) {
#pragma unroll
                for (int kw = 0; kw < 4; kw++) {
                    int iw = ow * 2 - 1 + kw;
                    if ((unsigned)iw < 128u) a += xp[ih * 128 + iw] * sK[c][kh * 4 + kw];
                }
            }
        }
        sD[c][ow] = a;
    }
    __syncthreads();

    int tx = tid & 63, py = tid >> 6;
    float w0 = sW[0][tx], w1 = sW[1][tx], w2 = sW[2][tx], bb = sB[tx];
    float s = 0.f, q = 0.f;
#pragma unroll
    for (int pix = py; pix < 64; pix += 4) {
        float v = fmaf(sD[0][pix], w0, fmaf(sD[1][pix], w1, fmaf(sD[2][pix], w2, bb)));
        v = v > 0.f ? v : 0.2f * v;
        Y[(((size_t)b * 64 + oh) * 64 + pix) * 64 + tx] = v;
        s += v; q += v * v;
    }
    atomicAdd(&sSum[tx], s);
    atomicAdd(&sSq[tx], q);
    __syncthreads();
    if (tid < 64) { atomicAdd(&sums[tid], sSum[tid]); atomicAdd(&sums[64 + tid], sSq[tid]); }
}

// ---------------- generic depthwise conv (NHWC, BN affine applied on load) --
__global__ void dwconv_kernel(const float* __restrict__ Yin, const float* __restrict__ ss,
                              const float* __restrict__ kern, float* __restrict__ out,
                              int C, int Ct, int cpb, int Hin, int Win, int Hout, int Wout,
                              int ksz, int stride, int pad)
{
    int b  = blockIdx.y;
    int px = blockIdx.x * cpb + threadIdx.x / Ct;
    int c0 = threadIdx.x % Ct;
    if (threadIdx.x >= Ct * cpb) return;
    if (px >= Hout * Wout) return;
    int oh = px / Wout, ow = px % Wout;
    for (int c = c0; c < C; c += Ct) {
        float sc = ss[c], sh = ss[C + c];
        const float* kb = kern + ((size_t)b * C + c) * ksz * ksz;
        float a = 0.f;
        for (int kh = 0; kh < ksz; kh++) {
            int ih = oh * stride - pad + kh;
            if ((unsigned)ih >= (unsigned)Hin) continue;
            for (int kw = 0; kw < ksz; kw++) {
                int iw = ow * stride - pad + kw;
                if ((unsigned)iw >= (unsigned)Win) continue;
                float v = Yin[(((size_t)b * Hin + ih) * Win + iw) * C + c];
                a += (v * sc + sh) * kb[kh * ksz + kw];
            }
        }
        out[(((size_t)b * Hout + oh) * Wout + ow) * C + c] = a;
    }
}

// ---------------- channel mixer GEMM (f32x2 FMA, register prefetch) ---------
// X: M x K row-major, Wt: K x N row-major.
// MODE 0: Y[m*N+n] = lrelu(XW+b), accumulate per-channel sum/sumsq.
// MODE 1: NCHW output with sigmoid (spatial = H*W).
template<int BM, int BN, int TM, int TN, int MODE>
__global__ __launch_bounds__(256) void mix2_kernel(
    const float* __restrict__ X, const float* __restrict__ Wt,
    const float* __restrict__ bias, float* __restrict__ Y,
    float* __restrict__ sums, int M, int N, int K, int spatial)
{
    constexpr int BK = 16;
    constexpr int PAD = 4;
    __shared__ float As[BK][BM + PAD];
    __shared__ float Bs[BK][BN + PAD];
    __shared__ float sSum[BN], sSq[BN];

    const int tid = threadIdx.x;
    const int tx = tid & 15, ty = tid >> 4;       // 16 x 16 thread grid
    const int m0 = blockIdx.x * BM, n0 = blockIdx.y * BN;

    if (MODE == 0) {
        for (int i = tid; i < BN; i += 256) { sSum[i] = 0.f; sSq[i] = 0.f; }
    }

    constexpr int nA = BM * BK / (4 * 256);
    constexpr int nB = BN * BK / (4 * 256);
    float4 ra[nA], rb[nB];

    const float* Xp = X + (size_t)m0 * K;
    const float* Wp = Wt + n0;

    // prefetch first tile into registers
#pragma unroll
    for (int v = 0; v < nA; v++) {
        int idx = tid + v * 256;
        int m = idx >> 2, kq = idx & 3;
        ra[v] = *(const float4*)(Xp + (size_t)m * K + kq * 4);
    }
#pragma unroll
    for (int v = 0; v < nB; v++) {
        int idx = tid + v * 256;
        int k = idx / (BN / 4), nq = idx % (BN / 4);
        rb[v] = *(const float4*)(Wp + (size_t)k * N + nq * 4);
    }

    ull acc[TM][TN / 2];
#pragma unroll
    for (int i = 0; i < TM; i++)
#pragma unroll
        for (int j = 0; j < TN / 2; j++) acc[i][j] = 0ULL;

    const int nk = K / BK;
    for (int kt = 0; kt < nk; kt++) {
        // commit register tile to shared
#pragma unroll
        for (int v = 0; v < nA; v++) {
            int idx = tid + v * 256;
            int m = idx >> 2, kq = idx & 3;
            As[kq * 4 + 0][m] = ra[v].x;
            As[kq * 4 + 1][m] = ra[v].y;
            As[kq * 4 + 2][m] = ra[v].z;
            As[kq * 4 + 3][m] = ra[v].w;
        }
#pragma unroll
        for (int v = 0; v < nB; v++) {
            int idx = tid + v * 256;
            int k = idx / (BN / 4), nq = idx % (BN / 4);
            *(float4*)&Bs[k][nq * 4] = rb[v];
        }
        __syncthreads();

        if (kt + 1 < nk) {
            const float* Xn = Xp + (kt + 1) * BK;
            const float* Wn = Wp + (size_t)(kt + 1) * BK * N;
#pragma unroll
            for (int v = 0; v < nA; v++) {
                int idx = tid + v * 256;
                int m = idx >> 2, kq = idx & 3;
                ra[v] = *(const float4*)(Xn + (size_t)m * K + kq * 4);
            }
#pragma unroll
            for (int v = 0; v < nB; v++) {
                int idx = tid + v * 256;
                int k = idx / (BN / 4), nq = idx % (BN / 4);
                rb[v] = *(const float4*)(Wn + (size_t)k * N + nq * 4);
            }
        }

#pragma unroll
        for (int kk = 0; kk < BK; kk++) {
            float a[TM];
#pragma unroll
            for (int i = 0; i < TM; i += 4) {
                float4 t = *(const float4*)&As[kk][ty * TM + i];
                a[i] = t.x; a[i + 1] = t.y; a[i + 2] = t.z; a[i + 3] = t.w;
            }
            // b fragment: two float4 chunks at tx*4 and BN/2 + tx*4 (conflict-free LDS.128)
            float4 t0 = *(const float4*)&Bs[kk][tx * 4];
            float4 t1 = *(const float4*)&Bs[kk][BN / 2 + tx * 4];
            ull b2[4];
            b2[0] = pack2(t0.x, t0.y); b2[1] = pack2(t0.z, t0.w);
            b2[2] = pack2(t1.x, t1.y); b2[3] = pack2(t1.z, t1.w);
#pragma unroll
            for (int i = 0; i < TM; i++) {
                ull ad = dup2(a[i]);
#pragma unroll
                for (int j = 0; j < TN / 2; j++) fma2(acc[i][j], ad, b2[j]);
            }
        }
        __syncthreads();
    }

    // epilogue
    float4 bias0 = *(const float4*)(bias + n0 + tx * 4);
    float4 bias1 = *(const float4*)(bias + n0 + BN / 2 + tx * 4);
    float bfr[8] = {bias0.x, bias0.y, bias0.z, bias0.w, bias1.x, bias1.y, bias1.z, bias1.w};

    if (MODE == 0) {
        float cs[8], cq[8];
#pragma unroll
        for (int j = 0; j < 8; j++) { cs[j] = 0.f; cq[j] = 0.f; }
#pragma unroll
        for (int i = 0; i < TM; i++) {
            int m = m0 + ty * TM + i;
            float vo[8];
#pragma unroll
            for (int j = 0; j < TN / 2; j++) {
                float2 p = unpack2(acc[i][j]);
                vo[2 * j] = p.x; vo[2 * j + 1] = p.y;
            }
#pragma unroll
            for (int j = 0; j < 8; j++) {
                float v = vo[j] + bfr[j];
                v = v > 0.f ? v : 0.2f * v;
                vo[j] = v;
                cs[j] += v; cq[j] += v * v;
            }
            float* yp = Y + (size_t)m * N + n0;
            *(float4*)(yp + tx * 4)          = make_float4(vo[0], vo[1], vo[2], vo[3]);
            *(float4*)(yp + BN / 2 + tx * 4) = make_float4(vo[4], vo[5], vo[6], vo[7]);
        }
#pragma unroll
        for (int j = 0; j < 4; j++) {
            atomicAdd(&sSum[tx * 4 + j], cs[j]);
            atomicAdd(&sSq[tx * 4 + j], cq[j]);
            atomicAdd(&sSum[BN / 2 + tx * 4 + j], cs[4 + j]);
            atomicAdd(&sSq[BN / 2 + tx * 4 + j], cq[4 + j]);
        }
        __syncthreads();
        for (int i = tid; i < BN; i += 256) {
            atomicAdd(&sums[n0 + i],     sSum[i]);
            atomicAdd(&sums[N + n0 + i], sSq[i]);
        }
    } else {
#pragma unroll
        for (int i = 0; i < TM; i++) {
            int m = m0 + ty * TM + i;
            int b = m / spatial, p = m % spatial;
            float vo[8];
#pragma unroll
            for (int j = 0; j < TN / 2; j++) {
                float2 pr = unpack2(acc[i][j]);
                vo[2 * j] = pr.x; vo[2 * j + 1] = pr.y;
            }
#pragma unroll
            for (int j = 0; j < 8; j++) {
                int n = n0 + (j < 4 ? tx * 4 + j : BN / 2 + tx * 4 + (j - 4));
                float v = vo[j] + bfr[j];
                v = 1.f / (1.f + expf(-v));
                Y[((size_t)b * N + n) * spatial + p] = v;
            }
        }
    }
}

// ---------------- BN helpers -------------------------------------------------
__global__ void zero_kernel(float* p, int n)
{
    int i = blockIdx.x * blockDim.x + threadIdx.x;
    if (i < n) p[i] = 0.f;
}

__global__ void bn_final_kernel(const float* __restrict__ sums,
                                const float* __restrict__ g, const float* __restrict__ b,
                                float* __restrict__ ss, int C, float invCnt)
{
    int c = blockIdx.x * blockDim.x + threadIdx.x;
    if (c >= C) return;
    float mean = sums[c] * invCnt;
    float var  = sums[C + c] * invCnt - mean * mean;
    float sc = g[c] * rsqrtf(var + 1e-5f);
    ss[c] = sc;
    ss[C + c] = b[c] - mean * sc;
}

__global__ void write_label_kernel(const int* __restrict__ label, float* __restrict__ out, int n)
{
    int i = threadIdx.x;
    if (i < n) out[i] = (float)label[i];
}

// ---------------- launcher ---------------------------------------------------
extern "C" void kernel_launch(void* const* d_in, const int* in_sizes, int n_in,
                              void* d_out, int out_size)
{
    const float* input = (const float*)d_in[0];
    const int*   label = (const int*)d_in[1];
    const float* emb   = (const float*)d_in[2];
    const float* lw[5] = {(const float*)d_in[3], (const float*)d_in[5], (const float*)d_in[7],
                          (const float*)d_in[9], (const float*)d_in[11]};
    const float* lb[5] = {(const float*)d_in[4], (const float*)d_in[6], (const float*)d_in[8],
                          (const float*)d_in[10], (const float*)d_in[12]};
    const float* cmw[5] = {(const float*)d_in[13], (const float*)d_in[15], (const float*)d_in[17],
                           (const float*)d_in[19], (const float*)d_in[21]};
    const float* cmb[5] = {(const float*)d_in[14], (const float*)d_in[16], (const float*)d_in[18],
                           (const float*)d_in[20], (const float*)d_in[22]};
    const float* bng[4] = {(const float*)d_in[23], (const float*)d_in[25],
                           (const float*)d_in[27], (const float*)d_in[29]};
    const float* bnb[4] = {(const float*)d_in[24], (const float*)d_in[26],
                           (const float*)d_in[28], (const float*)d_in[30]};

    float *pA, *pB, *pDw, *pK, *pSums, *pSS;
    cudaGetSymbolAddress((void**)&pA,    g_bufA);
    cudaGetSymbolAddress((void**)&pB,    g_bufB);
    cudaGetSymbolAddress((void**)&pDw,   g_dw);
    cudaGetSymbolAddress((void**)&pK,    g_kern);
    cudaGetSymbolAddress((void**)&pSums, g_sums);
    cudaGetSymbolAddress((void**)&pSS,   g_ss);

    float* out = (float*)d_out;

    // ---------- Layer 1 (fused): dwconv(3ch,128->64) + mix(3->64) + bn1 ----------
    {
        int CK = 3 * 16;
        dynk_kernel<<<dim3(1, 128), 64>>>(label, emb, lw[0], lb[0], pK, CK);
        zero_kernel<<<1, 128>>>(pSums, 128);
        l1_fused_kernel<<<dim3(64, 128), 256>>>(input, pK, cmw[0], cmb[0], pA, pSums);
        bn_final_kernel<<<1, 64>>>(pSums, bng[0], bnb[0], pSS, 64, 1.f / (float)(128 * 64 * 64));
    }
    // ---------- Layer 2: dwconv(64ch,64->32,k4) + mix(64->128) + bn2 ----------
    {
        int CK = 64 * 16;
        dynk_kernel<<<dim3(4, 128), 256>>>(label, emb, lw[1], lb[1], pK, CK);
        dwconv_kernel<<<dim3(256, 128), 256>>>(pA, pSS, pK, pDw,
                                               64, 64, 4, 64, 64, 32, 32, 4, 2, 1);
        zero_kernel<<<1, 256>>>(pSums, 256);
        int M = 128 * 32 * 32, N = 128, K = 64;
        mix2_kernel<128, 128, 8, 8, 0><<<dim3(M / 128, N / 128), 256>>>(
            pDw, cmw[1], cmb[1], pB, pSums, M, N, K, 0);
        bn_final_kernel<<<1, 128>>>(pSums, bng[1], bnb[1], pSS, 128, 1.f / (float)M);
    }
    // ---------- Layer 3: dwconv(128ch,32->16,k3) + mix(128->256) + bn3 ----------
    {
        int CK = 128 * 9;
        dynk_kernel<<<dim3(5, 128), 256>>>(label, emb, lw[2], lb[2], pK, CK);
        dwconv_kernel<<<dim3(128, 128), 256>>>(pB, pSS, pK, pDw,
                                               128, 128, 2, 32, 32, 16, 16, 3, 2, 1);
        zero_kernel<<<1, 512>>>(pSums, 512);
        int M = 128 * 16 * 16, N = 256, K = 128;
        mix2_kernel<128, 128, 8, 8, 0><<<dim3(M / 128, N / 128), 256>>>(
            pDw, cmw[2], cmb[2], pA, pSums, M, N, K, 0);
        bn_final_kernel<<<1, 256>>>(pSums, bng[2], bnb[2], pSS, 256, 1.f / (float)M);
    }
    // ---------- Layer 4: dwconv(256ch,16->8,k4) + mix(256->512) + bn4 ----------
    {
        int CK = 256 * 16;
        dynk_kernel<<<dim3(16, 128), 256>>>(label, emb, lw[3], lb[3], pK, CK);
        dwconv_kernel<<<dim3(64, 128), 256>>>(pA, pSS, pK, pDw,
                                              256, 256, 1, 16, 16, 8, 8, 4, 2, 1);
        zero_kernel<<<1, 1024>>>(pSums, 1024);
        int M = 128 * 8 * 8, N = 512, K = 256;
        mix2_kernel<128, 128, 8, 8, 0><<<dim3(M / 128, N / 128), 256>>>(
            pDw, cmw[3], cmb[3], pB, pSums, M, N, K, 0);
        bn_final_kernel<<<1, 512>>>(pSums, bng[3], bnb[3], pSS, 512, 1.f / (float)M);
    }
    // ---------- Layer 5: dwconv(512ch,8->7,k2,s1,p0) + mix(512->512) + sigmoid -> d_out (NCHW)
    {
        int CK = 512 * 4;
        dynk_kernel<<<dim3(8, 128), 256>>>(label, emb, lw[4], lb[4], pK, CK);
        dwconv_kernel<<<dim3(49, 128), 256>>>(pB, pSS, pK, pDw,
                                              512, 256, 1, 8, 8, 7, 7, 2, 1, 0);
        int M = 128 * 49, N = 512, K = 512;
        mix2_kernel<64, 128, 4, 8, 1><<<dim3(M / 64, N / 128), 256>>>(
            pDw, cmw[4], cmb[4], out, nullptr, M, N, K, 49);
    }
    // ---------- label tail (if output concatenates (z, label)) ----------
    {
        long long zElems = 128LL * 512 * 49;
        long long tail = (long long)out_size - zElems;
        if (tail > 0) {
            int n = tail > 128 ? 128 : (int)tail;
            write_label_kernel<<<1, 128>>>(label, out + zElems, n);
        }
    }
}

// round 3
// speedup vs baseline: 1.3394x; 1.0359x over previous
#include <cuda_runtime.h>
#include <cuda_bf16.h>
#include <cstddef>

// ---------------- scratch (device globals; no allocation allowed) ----------
__device__ float g_bufA[33554432];   // ping (max: L1 out 128*64*64*64)
__device__ float g_bufB[16777216];   // pong (max: L2 out 128*128*32*32)
__device__ float g_dw[8388608];      // dwconv out (max: L2 in 128*64*32*32)
__device__ float g_kern[1179648];    // all 5 dyn kernel sets (128*8368 = 1,071,104)
__device__ float g_sums[2048];       // per-layer per-channel sum/sumsq regions
__device__ float g_ss[1024];         // per-channel scale / shift

// dyn-kernel region offsets (floats)
#define KOFF1 0
#define KOFF2 6144        // 128*48
#define KOFF3 137216      // +128*1024
#define KOFF4 284672      // +128*1152
#define KOFF5 808960      // +128*4096
// BN sums region offsets
#define SOFF1 0
#define SOFF2 128
#define SOFF3 384
#define SOFF4 896

// ---------------- bf16 hi/lo split + pack -----------------------------------
__device__ __forceinline__ void split_pack(float x0, float x1, unsigned& h, unsigned& l)
{
    __nv_bfloat16 h0 = __float2bfloat16(x0);
    __nv_bfloat16 h1 = __float2bfloat16(x1);
    __nv_bfloat16 l0 = __float2bfloat16(x0 - __bfloat162float(h0));
    __nv_bfloat16 l1 = __float2bfloat16(x1 - __bfloat162float(h1));
    h = (unsigned)__bfloat16_as_ushort(h0) | ((unsigned)__bfloat16_as_ushort(h1) << 16);
    l = (unsigned)__bfloat16_as_ushort(l0) | ((unsigned)__bfloat16_as_ushort(l1) << 16);
}

__device__ __forceinline__ void mma_bf16(float* c, unsigned a0, unsigned a1, unsigned a2,
                                         unsigned a3, unsigned b0, unsigned b1)
{
    asm volatile(
        "mma.sync.aligned.m16n8k16.row.col.f32.bf16.bf16.f32 "
        "{%0,%1,%2,%3}, {%4,%5,%6,%7}, {%8,%9}, {%0,%1,%2,%3};\n"
        : "+f"(c[0]), "+f"(c[1]), "+f"(c[2]), "+f"(c[3])
        : "r"(a0), "r"(a1), "r"(a2), "r"(a3), "r"(b0), "r"(b1));
}

// ---------------- prep: all dyn kernels (tanh(e@W+b)) + zero sums -----------
__global__ void prep_kernel(const int* __restrict__ label, const float* __restrict__ emb,
                            const float* __restrict__ w1, const float* __restrict__ b1,
                            const float* __restrict__ w2, const float* __restrict__ b2,
                            const float* __restrict__ w3, const float* __restrict__ b3,
                            const float* __restrict__ w4, const float* __restrict__ b4,
                            const float* __restrict__ w5, const float* __restrict__ b5,
                            float* __restrict__ kern, float* __restrict__ sums)
{
    int b = blockIdx.y;
    int i = blockIdx.x * 256 + threadIdx.x;
    if (b == 0 && i < 1920) sums[i] = 0.f;

    const float* W; const float* bb; int ck, off, j;
    if (i < 48)            { W = w1; bb = b1; ck = 48;   off = KOFF1; j = i; }
    else if (i < 1072)     { W = w2; bb = b2; ck = 1024; off = KOFF2; j = i - 48; }
    else if (i < 2224)     { W = w3; bb = b3; ck = 1152; off = KOFF3; j = i - 1072; }
    else if (i < 6320)     { W = w4; bb = b4; ck = 4096; off = KOFF4; j = i - 2224; }
    else if (i < 8368)     { W = w5; bb = b5; ck = 2048; off = KOFF5; j = i - 6320; }
    else return;

    const float* e = emb + label[b] * 5;
    float a = bb[j];
#pragma unroll
    for (int t = 0; t < 5; t++) a += e[t] * W[t * ck + j];
    kern[off + (size_t)b * ck + j] = tanhf(a);
}

// ---------------- layer 1 fused: dwconv(3ch) + mix(3->64) + lrelu + stats ---
__global__ __launch_bounds__(256) void l1_fused_kernel(
    const float* __restrict__ x, const float* __restrict__ kern,
    const float* __restrict__ W, const float* __restrict__ bias,
    float* __restrict__ Y, float* __restrict__ sums)
{
    __shared__ float sW[3][64];
    __shared__ float sB[64];
    __shared__ float sK[3][16];
    __shared__ float sD[3][64];
    __shared__ float sSum[64], sSq[64];

    int b = blockIdx.y, oh = blockIdx.x;
    int tid = threadIdx.x;

    if (tid < 192) sW[tid / 64][tid % 64] = W[tid];
    if (tid < 64) { sB[tid] = bias[tid]; sSum[tid] = 0.f; sSq[tid] = 0.f; }
    if (tid >= 192 && tid < 240) { int q = tid - 192; sK[q / 16][q % 16] = kern[(size_t)b * 48 + q]; }
    __syncthreads();

    if (tid < 192) {
        int c = tid / 64, ow = tid % 64;
        const float* xp = x + ((size_t)b * 3 + c) * 16384;
        float a = 0.f;
#pragma unroll
        for (int kh = 0; kh < 4; kh++) {
            int ih = oh * 2 - 1 + kh;
            if ((unsigned)ih < 128u) {
#pragma unroll
                for (int kw = 0; kw < 4; kw++) {
                    int iw = ow * 2 - 1 + kw;
                    if ((unsigned)iw < 128u) a += xp[ih * 128 + iw] * sK[c][kh * 4 + kw];
                }
            }
        }
        sD[c][ow] = a;
    }
    __syncthreads();

    int tx = tid & 63, py = tid >> 6;
    float w0 = sW[0][tx], w1 = sW[1][tx], w2 = sW[2][tx], bb = sB[tx];
    float s = 0.f, q = 0.f;
#pragma unroll
    for (int pix = py; pix < 64; pix += 4) {
        float v = fmaf(sD[0][pix], w0, fmaf(sD[1][pix], w1, fmaf(sD[2][pix], w2, bb)));
        v = v > 0.f ? v : 0.2f * v;
        Y[(((size_t)b * 64 + oh) * 64 + pix) * 64 + tx] = v;
        s += v; q += v * v;
    }
    atomicAdd(&sSum[tx], s);
    atomicAdd(&sSq[tx], q);
    __syncthreads();
    if (tid < 64) { atomicAdd(&sums[tid], sSum[tid]); atomicAdd(&sums[64 + tid], sSq[tid]); }
}

// ---------------- generic depthwise conv (NHWC, BN affine applied on load) --
__global__ void dwconv_kernel(const float* __restrict__ Yin, const float* __restrict__ ss,
                              const float* __restrict__ kern, float* __restrict__ out,
                              int C, int Ct, int cpb, int Hin, int Win, int Hout, int Wout,
                              int ksz, int stride, int pad)
{
    int b  = blockIdx.y;
    int px = blockIdx.x * cpb + threadIdx.x / Ct;
    int c0 = threadIdx.x % Ct;
    if (threadIdx.x >= Ct * cpb) return;
    if (px >= Hout * Wout) return;
    int oh = px / Wout, ow = px % Wout;
    for (int c = c0; c < C; c += Ct) {
        float sc = ss[c], sh = ss[C + c];
        const float* kb = kern + ((size_t)b * C + c) * ksz * ksz;
        float a = 0.f;
        for (int kh = 0; kh < ksz; kh++) {
            int ih = oh * stride - pad + kh;
            if ((unsigned)ih >= (unsigned)Hin) continue;
            for (int kw = 0; kw < ksz; kw++) {
                int iw = ow * stride - pad + kw;
                if ((unsigned)iw >= (unsigned)Win) continue;
                float v = Yin[(((size_t)b * Hin + ih) * Win + iw) * C + c];
                a += (v * sc + sh) * kb[kh * ksz + kw];
            }
        }
        out[(((size_t)b * Hout + oh) * Wout + ow) * C + c] = a;
    }
}

// ---------------- channel mixer GEMM: bf16x3 tensor-core --------------------
// X: M x K fp32 row-major.  Wt: K x N fp32 row-major.
// MODE 0: Y = lrelu(XW+b) row-major + per-channel sum/sumsq.
// MODE 1: sigmoid(XW+b) scattered to NCHW (spatial=H*W).
template<int MODE>
__global__ __launch_bounds__(256) void mix_mma_kernel(
    const float* __restrict__ X, const float* __restrict__ Wt,
    const float* __restrict__ bias, float* __restrict__ Y,
    float* __restrict__ sums, int M, int N, int K, int spatial)
{
    constexpr int BM = 128, BN = 128, BK = 32;
    constexpr int LDA = BK / 2 + 4;          // 20 u32 per row -> conflict-free frags
    __shared__ unsigned As_h[BM][LDA], As_l[BM][LDA];
    __shared__ unsigned Bs_h[BN][LDA], Bs_l[BN][LDA];
    __shared__ float sSum[BN], sSq[BN];

    const int tid  = threadIdx.x;
    const int wid  = tid >> 5, lane = tid & 31;
    const int g    = lane >> 2, tig = lane & 3;
    const int wm   = (wid >> 2) * 64;        // 2 warps in M
    const int wn   = (wid & 3) * 32;         // 4 warps in N
    const int m0   = blockIdx.x * BM, n0 = blockIdx.y * BN;

    if (MODE == 0) {
        for (int i = tid; i < BN; i += 256) { sSum[i] = 0.f; sSq[i] = 0.f; }
    }

    float acc[4][4][4];
#pragma unroll
    for (int mi = 0; mi < 4; mi++)
#pragma unroll
        for (int ni = 0; ni < 4; ni++)
#pragma unroll
            for (int r = 0; r < 4; r++) acc[mi][ni][r] = 0.f;

    const float* Xp = X + (size_t)m0 * K;
    const float* Wp = Wt + n0;

    float4 xa[4], wb[4];
    // prefetch tile 0
#pragma unroll
    for (int v = 0; v < 4; v++) {
        int idx = tid + 256 * v;
        int m = idx >> 3, q = idx & 7;
        xa[v] = *(const float4*)(Xp + (size_t)m * K + q * 4);
    }
#pragma unroll
    for (int v = 0; v < 2; v++) {
        int idx = tid + 256 * v;
        int j = idx >> 5, nc = idx & 31;
        wb[2 * v]     = *(const float4*)(Wp + (size_t)(2 * j) * N + 4 * nc);
        wb[2 * v + 1] = *(const float4*)(Wp + (size_t)(2 * j + 1) * N + 4 * nc);
    }

    const int nk = K / BK;
    for (int kt = 0; kt < nk; kt++) {
        if (kt > 0) __syncthreads();
        // commit regs -> smem with bf16 hi/lo split
#pragma unroll
        for (int v = 0; v < 4; v++) {
            int idx = tid + 256 * v;
            int m = idx >> 3, q = idx & 7;
            unsigned h0, l0, h1, l1;
            split_pack(xa[v].x, xa[v].y, h0, l0);
            split_pack(xa[v].z, xa[v].w, h1, l1);
            As_h[m][2 * q] = h0; As_h[m][2 * q + 1] = h1;
            As_l[m][2 * q] = l0; As_l[m][2 * q + 1] = l1;
        }
#pragma unroll
        for (int v = 0; v < 2; v++) {
            int idx = tid + 256 * v;
            int j = idx >> 5, nc = idx & 31;
            float4 f0 = wb[2 * v], f1 = wb[2 * v + 1];
            unsigned h, l;
            split_pack(f0.x, f1.x, h, l); Bs_h[4 * nc + 0][j] = h; Bs_l[4 * nc + 0][j] = l;
            split_pack(f0.y, f1.y, h, l); Bs_h[4 * nc + 1][j] = h; Bs_l[4 * nc + 1][j] = l;
            split_pack(f0.z, f1.z, h, l); Bs_h[4 * nc + 2][j] = h; Bs_l[4 * nc + 2][j] = l;
            split_pack(f0.w, f1.w, h, l); Bs_h[4 * nc + 3][j] = h; Bs_l[4 * nc + 3][j] = l;
        }
        __syncthreads();

        if (kt + 1 < nk) {
            const float* Xn = Xp + (kt + 1) * BK;
            const float* Wn = Wp + (size_t)(kt + 1) * BK * N;
#pragma unroll
            for (int v = 0; v < 4; v++) {
                int idx = tid + 256 * v;
                int m = idx >> 3, q = idx & 7;
                xa[v] = *(const float4*)(Xn + (size_t)m * K + q * 4);
            }
#pragma unroll
            for (int v = 0; v < 2; v++) {
                int idx = tid + 256 * v;
                int j = idx >> 5, nc = idx & 31;
                wb[2 * v]     = *(const float4*)(Wn + (size_t)(2 * j) * N + 4 * nc);
                wb[2 * v + 1] = *(const float4*)(Wn + (size_t)(2 * j + 1) * N + 4 * nc);
            }
        }

#pragma unroll
        for (int s = 0; s < 2; s++) {
            unsigned ah[4][4], al[4][4], bh[4][2], bl[4][2];
#pragma unroll
            for (int mi = 0; mi < 4; mi++) {
                int r0 = wm + 16 * mi + g, r1 = r0 + 8;
                int c0 = 8 * s + tig;
                ah[mi][0] = As_h[r0][c0];     ah[mi][1] = As_h[r1][c0];
                ah[mi][2] = As_h[r0][c0 + 4]; ah[mi][3] = As_h[r1][c0 + 4];
                al[mi][0] = As_l[r0][c0];     al[mi][1] = As_l[r1][c0];
                al[mi][2] = As_l[r0][c0 + 4]; al[mi][3] = As_l[r1][c0 + 4];
            }
#pragma unroll
            for (int ni = 0; ni < 4; ni++) {
                int n = wn + 8 * ni + g;
                int c0 = 8 * s + tig;
                bh[ni][0] = Bs_h[n][c0]; bh[ni][1] = Bs_h[n][c0 + 4];
                bl[ni][0] = Bs_l[n][c0]; bl[ni][1] = Bs_l[n][c0 + 4];
            }
#pragma unroll
            for (int mi = 0; mi < 4; mi++)
#pragma unroll
                for (int ni = 0; ni < 4; ni++) {
                    mma_bf16(acc[mi][ni], ah[mi][0], ah[mi][1], ah[mi][2], ah[mi][3],
                             bh[ni][0], bh[ni][1]);
                    mma_bf16(acc[mi][ni], ah[mi][0], ah[mi][1], ah[mi][2], ah[mi][3],
                             bl[ni][0], bl[ni][1]);
                    mma_bf16(acc[mi][ni], al[mi][0], al[mi][1], al[mi][2], al[mi][3],
                             bh[ni][0], bh[ni][1]);
                }
        }
    }

    // ---------------- epilogue ----------------
    float2 bv[4];
#pragma unroll
    for (int ni = 0; ni < 4; ni++)
        bv[ni] = *(const float2*)(bias + n0 + wn + 8 * ni + 2 * tig);

    if (MODE == 0) {
        float cs[4][2], cq[4][2];
#pragma unroll
        for (int ni = 0; ni < 4; ni++) { cs[ni][0] = cs[ni][1] = 0.f; cq[ni][0] = cq[ni][1] = 0.f; }
#pragma unroll
        for (int mi = 0; mi < 4; mi++) {
            int r0 = m0 + wm + 16 * mi + g, r1 = r0 + 8;
#pragma unroll
            for (int ni = 0; ni < 4; ni++) {
                int n = n0 + wn + 8 * ni + 2 * tig;
                float v0 = acc[mi][ni][0] + bv[ni].x;
                float v1 = acc[mi][ni][1] + bv[ni].y;
                float v2 = acc[mi][ni][2] + bv[ni].x;
                float v3 = acc[mi][ni][3] + bv[ni].y;
                v0 = v0 > 0.f ? v0 : 0.2f * v0;
                v1 = v1 > 0.f ? v1 : 0.2f * v1;
                v2 = v2 > 0.f ? v2 : 0.2f * v2;
                v3 = v3 > 0.f ? v3 : 0.2f * v3;
                *(float2*)(Y + (size_t)r0 * N + n) = make_float2(v0, v1);
                *(float2*)(Y + (size_t)r1 * N + n) = make_float2(v2, v3);
                cs[ni][0] += v0 + v2; cs[ni][1] += v1 + v3;
                cq[ni][0] += v0 * v0 + v2 * v2; cq[ni][1] += v1 * v1 + v3 * v3;
            }
        }
#pragma unroll
        for (int ni = 0; ni < 4; ni++) {
            int n = wn + 8 * ni + 2 * tig;
            atomicAdd(&sSum[n],     cs[ni][0]);
            atomicAdd(&sSum[n + 1], cs[ni][1]);
            atomicAdd(&sSq[n],      cq[ni][0]);
            atomicAdd(&sSq[n + 1],  cq[ni][1]);
        }
        __syncthreads();
        for (int i = tid; i < BN; i += 256) {
            atomicAdd(&sums[n0 + i],     sSum[i]);
            atomicAdd(&sums[N + n0 + i], sSq[i]);
        }
    } else {
#pragma unroll
        for (int mi = 0; mi < 4; mi++) {
            int r0 = m0 + wm + 16 * mi + g, r1 = r0 + 8;
            int b0i = r0 / spatial, p0 = r0 % spatial;
            int b1i = r1 / spatial, p1 = r1 % spatial;
#pragma unroll
            for (int ni = 0; ni < 4; ni++) {
                int n = n0 + wn + 8 * ni + 2 * tig;
                float v0 = acc[mi][ni][0] + bv[ni].x;
                float v1 = acc[mi][ni][1] + bv[ni].y;
                float v2 = acc[mi][ni][2] + bv[ni].x;
                float v3 = acc[mi][ni][3] + bv[ni].y;
                v0 = 1.f / (1.f + expf(-v0));
                v1 = 1.f / (1.f + expf(-v1));
                v2 = 1.f / (1.f + expf(-v2));
                v3 = 1.f / (1.f + expf(-v3));
                Y[((size_t)b0i * N + n)     * spatial + p0] = v0;
                Y[((size_t)b0i * N + n + 1) * spatial + p0] = v1;
                Y[((size_t)b1i * N + n)     * spatial + p1] = v2;
                Y[((size_t)b1i * N + n + 1) * spatial + p1] = v3;
            }
        }
    }
}

// ---------------- BN helpers -------------------------------------------------
__global__ void bn_final_kernel(const float* __restrict__ sums,
                                const float* __restrict__ g, const float* __restrict__ b,
                                float* __restrict__ ss, int C, float invCnt)
{
    int c = blockIdx.x * blockDim.x + threadIdx.x;
    if (c >= C) return;
    float mean = sums[c] * invCnt;
    float var  = sums[C + c] * invCnt - mean * mean;
    float sc = g[c] * rsqrtf(var + 1e-5f);
    ss[c] = sc;
    ss[C + c] = b[c] - mean * sc;
}

__global__ void write_label_kernel(const int* __restrict__ label, float* __restrict__ out, int n)
{
    int i = threadIdx.x;
    if (i < n) out[i] = (float)label[i];
}

// ---------------- launcher ---------------------------------------------------
extern "C" void kernel_launch(void* const* d_in, const int* in_sizes, int n_in,
                              void* d_out, int out_size)
{
    const float* input = (const float*)d_in[0];
    const int*   label = (const int*)d_in[1];
    const float* emb   = (const float*)d_in[2];
    const float* lw[5] = {(const float*)d_in[3], (const float*)d_in[5], (const float*)d_in[7],
                          (const float*)d_in[9], (const float*)d_in[11]};
    const float* lb[5] = {(const float*)d_in[4], (const float*)d_in[6], (const float*)d_in[8],
                          (const float*)d_in[10], (const float*)d_in[12]};
    const float* cmw[5] = {(const float*)d_in[13], (const float*)d_in[15], (const float*)d_in[17],
                           (const float*)d_in[19], (const float*)d_in[21]};
    const float* cmb[5] = {(const float*)d_in[14], (const float*)d_in[16], (const float*)d_in[18],
                           (const float*)d_in[20], (const float*)d_in[22]};
    const float* bng[4] = {(const float*)d_in[23], (const float*)d_in[25],
                           (const float*)d_in[27], (const float*)d_in[29]};
    const float* bnb[4] = {(const float*)d_in[24], (const float*)d_in[26],
                           (const float*)d_in[28], (const float*)d_in[30]};

    float *pA, *pB, *pDw, *pK, *pSums, *pSS;
    cudaGetSymbolAddress((void**)&pA,    g_bufA);
    cudaGetSymbolAddress((void**)&pB,    g_bufB);
    cudaGetSymbolAddress((void**)&pDw,   g_dw);
    cudaGetSymbolAddress((void**)&pK,    g_kern);
    cudaGetSymbolAddress((void**)&pSums, g_sums);
    cudaGetSymbolAddress((void**)&pSS,   g_ss);

    float* out = (float*)d_out;

    // ---------- prep: all dyn kernels + zero all sums ----------
    prep_kernel<<<dim3(33, 128), 256>>>(label, emb, lw[0], lb[0], lw[1], lb[1],
                                        lw[2], lb[2], lw[3], lb[3], lw[4], lb[4],
                                        pK, pSums);

    // ---------- Layer 1 (fused): dwconv(3ch,128->64) + mix(3->64) + bn1 ----------
    l1_fused_kernel<<<dim3(64, 128), 256>>>(input, pK + KOFF1, cmw[0], cmb[0], pA, pSums + SOFF1);
    bn_final_kernel<<<1, 64>>>(pSums + SOFF1, bng[0], bnb[0], pSS, 64, 1.f / (float)(128 * 64 * 64));

    // ---------- Layer 2: dwconv(64ch,64->32,k4) + mix(64->128) + bn2 ----------
    {
        dwconv_kernel<<<dim3(256, 128), 256>>>(pA, pSS, pK + KOFF2, pDw,
                                               64, 64, 4, 64, 64, 32, 32, 4, 2, 1);
        int M = 128 * 32 * 32, N = 128, K = 64;
        mix_mma_kernel<0><<<dim3(M / 128, N / 128), 256>>>(
            pDw, cmw[1], cmb[1], pB, pSums + SOFF2, M, N, K, 0);
        bn_final_kernel<<<1, 128>>>(pSums + SOFF2, bng[1], bnb[1], pSS, 128, 1.f / (float)M);
    }
    // ---------- Layer 3: dwconv(128ch,32->16,k3) + mix(128->256) + bn3 ----------
    {
        dwconv_kernel<<<dim3(128, 128), 256>>>(pB, pSS, pK + KOFF3, pDw,
                                               128, 128, 2, 32, 32, 16, 16, 3, 2, 1);
        int M = 128 * 16 * 16, N = 256, K = 128;
        mix_mma_kernel<0><<<dim3(M / 128, N / 128), 256>>>(
            pDw, cmw[2], cmb[2], pA, pSums + SOFF3, M, N, K, 0);
        bn_final_kernel<<<1, 256>>>(pSums + SOFF3, bng[2], bnb[2], pSS, 256, 1.f / (float)M);
    }
    // ---------- Layer 4: dwconv(256ch,16->8,k4) + mix(256->512) + bn4 ----------
    {
        dwconv_kernel<<<dim3(64, 128), 256>>>(pA, pSS, pK + KOFF4, pDw,
                                              256, 256, 1, 16, 16, 8, 8, 4, 2, 1);
        int M = 128 * 8 * 8, N = 512, K = 256;
        mix_mma_kernel<0><<<dim3(M / 128, N / 128), 256>>>(
            pDw, cmw[3], cmb[3], pB, pSums + SOFF4, M, N, K, 0);
        bn_final_kernel<<<1, 512>>>(pSums + SOFF4, bng[3], bnb[3], pSS, 512, 1.f / (float)M);
    }
    // ---------- Layer 5: dwconv(512ch,8->7,k2,s1,p0) + mix(512->512) + sigmoid -> d_out
    {
        dwconv_kernel<<<dim3(49, 128), 256>>>(pB, pSS, pK + KOFF5, pDw,
                                              512, 256, 1, 8, 8, 7, 7, 2, 1, 0);
        int M = 128 * 49, N = 512, K = 512;
        mix_mma_kernel<1><<<dim3(M / 128, N / 128), 256>>>(
            pDw, cmw[4], cmb[4], out, nullptr, M, N, K, 49);
    }
    // ---------- label tail (if output concatenates (z, label)) ----------
    {
        long long zElems = 128LL * 512 * 49;
        long long tail = (long long)out_size - zElems;
        if (tail > 0) {
            int n = tail > 128 ? 128 : (int)tail;
            write_label_kernel<<<1, 128>>>(label, out + zElems, n);
        }
    }
}

// round 4
// speedup vs baseline: 2.0511x; 1.5313x over previous
#include <cuda_runtime.h>
#include <cuda_bf16.h>
#include <cstddef>

// ---------------- scratch (device globals; no allocation allowed) ----------
__device__ float g_bufA[33554432];   // ping (max: L1 out 128*64*64*64)
__device__ float g_bufB[16777216];   // pong (max: L2 out 128*128*32*32)
__device__ float g_dw[8388608];      // dwconv out (max: L2 in 128*64*32*32)
__device__ float g_kern[1179648];    // all 5 dyn kernel sets
__device__ float g_sums[2048];       // per-layer per-channel sum/sumsq regions

// dyn-kernel region offsets (floats)
#define KOFF1 0
#define KOFF2 6144        // 128*48
#define KOFF3 137216      // +128*1024
#define KOFF4 284672      // +128*1152
#define KOFF5 808960      // +128*4096
// BN sums region offsets
#define SOFF1 0
#define SOFF2 128
#define SOFF3 384
#define SOFF4 896

// ---------------- bf16 hi/lo split + pack -----------------------------------
__device__ __forceinline__ void split_pack(float x0, float x1, unsigned& h, unsigned& l)
{
    __nv_bfloat16 h0 = __float2bfloat16(x0);
    __nv_bfloat16 h1 = __float2bfloat16(x1);
    __nv_bfloat16 l0 = __float2bfloat16(x0 - __bfloat162float(h0));
    __nv_bfloat16 l1 = __float2bfloat16(x1 - __bfloat162float(h1));
    h = (unsigned)__bfloat16_as_ushort(h0) | ((unsigned)__bfloat16_as_ushort(h1) << 16);
    l = (unsigned)__bfloat16_as_ushort(l0) | ((unsigned)__bfloat16_as_ushort(l1) << 16);
}

__device__ __forceinline__ void mma_bf16(float* c, unsigned a0, unsigned a1, unsigned a2,
                                         unsigned a3, unsigned b0, unsigned b1)
{
    asm volatile(
        "mma.sync.aligned.m16n8k16.row.col.f32.bf16.bf16.f32 "
        "{%0,%1,%2,%3}, {%4,%5,%6,%7}, {%8,%9}, {%0,%1,%2,%3};\n"
        : "+f"(c[0]), "+f"(c[1]), "+f"(c[2]), "+f"(c[3])
        : "r"(a0), "r"(a1), "r"(a2), "r"(a3), "r"(b0), "r"(b1));
}

// ---------------- prep: all dyn kernels (tanh(e@W+b)) + zero sums -----------
__global__ void prep_kernel(const int* __restrict__ label, const float* __restrict__ emb,
                            const float* __restrict__ w1, const float* __restrict__ b1,
                            const float* __restrict__ w2, const float* __restrict__ b2,
                            const float* __restrict__ w3, const float* __restrict__ b3,
                            const float* __restrict__ w4, const float* __restrict__ b4,
                            const float* __restrict__ w5, const float* __restrict__ b5,
                            float* __restrict__ kern, float* __restrict__ sums)
{
    int b = blockIdx.y;
    int i = blockIdx.x * 256 + threadIdx.x;
    if (b == 0 && i < 1920) sums[i] = 0.f;

    const float* W; const float* bb; int ck, off, j;
    if (i < 48)            { W = w1; bb = b1; ck = 48;   off = KOFF1; j = i; }
    else if (i < 1072)     { W = w2; bb = b2; ck = 1024; off = KOFF2; j = i - 48; }
    else if (i < 2224)     { W = w3; bb = b3; ck = 1152; off = KOFF3; j = i - 1072; }
    else if (i < 6320)     { W = w4; bb = b4; ck = 4096; off = KOFF4; j = i - 2224; }
    else if (i < 8368)     { W = w5; bb = b5; ck = 2048; off = KOFF5; j = i - 6320; }
    else return;

    const float* e = emb + label[b] * 5;
    float a = bb[j];
#pragma unroll
    for (int t = 0; t < 5; t++) a += e[t] * W[t * ck + j];
    kern[off + (size_t)b * ck + j] = tanhf(a);
}

// ---------------- layer 1 fused: dwconv(3ch) + mix(3->64) + lrelu + stats ---
__global__ __launch_bounds__(256) void l1_fused_kernel(
    const float* __restrict__ x, const float* __restrict__ kern,
    const float* __restrict__ W, const float* __restrict__ bias,
    float* __restrict__ Y, float* __restrict__ sums)
{
    __shared__ float sW[3][64];
    __shared__ float sB[64];
    __shared__ float sK[3][16];
    __shared__ float sD[3][64];
    __shared__ float sSum[64], sSq[64];

    int b = blockIdx.y, oh = blockIdx.x;
    int tid = threadIdx.x;

    if (tid < 192) sW[tid / 64][tid % 64] = W[tid];
    if (tid < 64) { sB[tid] = bias[tid]; sSum[tid] = 0.f; sSq[tid] = 0.f; }
    if (tid >= 192 && tid < 240) { int q = tid - 192; sK[q / 16][q % 16] = kern[(size_t)b * 48 + q]; }
    __syncthreads();

    if (tid < 192) {
        int c = tid / 64, ow = tid % 64;
        const float* xp = x + ((size_t)b * 3 + c) * 16384;
        float a = 0.f;
#pragma unroll
        for (int kh = 0; kh < 4; kh++) {
            int ih = oh * 2 - 1 + kh;
            if ((unsigned)ih < 128u) {
#pragma unroll
                for (int kw = 0; kw < 4; kw++) {
                    int iw = ow * 2 - 1 + kw;
                    if ((unsigned)iw < 128u) a += xp[ih * 128 + iw] * sK[c][kh * 4 + kw];
                }
            }
        }
        sD[c][ow] = a;
    }
    __syncthreads();

    int tx = tid & 63, py = tid >> 6;
    float w0 = sW[0][tx], w1 = sW[1][tx], w2 = sW[2][tx], bb = sB[tx];
    float s = 0.f, q = 0.f;
#pragma unroll
    for (int pix = py; pix < 64; pix += 4) {
        float v = fmaf(sD[0][pix], w0, fmaf(sD[1][pix], w1, fmaf(sD[2][pix], w2, bb)));
        v = v > 0.f ? v : 0.2f * v;
        Y[(((size_t)b * 64 + oh) * 64 + pix) * 64 + tx] = v;
        s += v; q += v * v;
    }
    atomicAdd(&sSum[tx], s);
    atomicAdd(&sSq[tx], q);
    __syncthreads();
    if (tid < 64) { atomicAdd(&sums[tid], sSum[tid]); atomicAdd(&sums[64 + tid], sSq[tid]); }
}

// ---------------- dwconv v2: smem weights, float4 channels, fused BN fold ---
// One block = (oh, b). Threads = (C/4) x Wout. Weights staged in smem [tap][c].
template<int KS, int C, int Hin, int Win, int Hout, int Wout, int Stride, int Pad>
__global__ __launch_bounds__((C / 4) * Wout) void dwconv_v2_kernel(
    const float* __restrict__ Yin, const float* __restrict__ sums,
    const float* __restrict__ bn_g, const float* __restrict__ bn_b, float invCnt,
    const float* __restrict__ kern, float* __restrict__ out)
{
    constexpr int KK = KS * KS;
    constexpr int CG = C / 4;
    constexpr int NT = CG * Wout;
    __shared__ __align__(16) float sW[KK][C];
    __shared__ __align__(16) float sSc[C], sSh[C];

    const int b = blockIdx.y, oh = blockIdx.x;
    const int tid = threadIdx.x;

    for (int c = tid; c < C; c += NT) {
        float mean = sums[c] * invCnt;
        float var  = sums[C + c] * invCnt - mean * mean;
        float sc = bn_g[c] * rsqrtf(var + 1e-5f);
        sSc[c] = sc;
        sSh[c] = bn_b[c] - mean * sc;
    }
    const float* kb = kern + (size_t)b * C * KK;
    for (int idx = tid; idx < C * KK; idx += NT) {
        int c = idx / KK, tap = idx % KK;
        sW[tap][c] = kb[idx];
    }
    __syncthreads();

    const int cg = tid % CG, ow = tid / CG;
    const int c = cg * 4;
    const float4 sc = *(const float4*)&sSc[c];
    const float4 sh = *(const float4*)&sSh[c];

    float4 acc = make_float4(0.f, 0.f, 0.f, 0.f);
#pragma unroll
    for (int kh = 0; kh < KS; kh++) {
        int ih = oh * Stride - Pad + kh;
        if ((unsigned)ih >= (unsigned)Hin) continue;
#pragma unroll
        for (int kw = 0; kw < KS; kw++) {
            int iw = ow * Stride - Pad + kw;
            if ((unsigned)iw >= (unsigned)Win) continue;
            float4 v = *(const float4*)&Yin[(((size_t)b * Hin + ih) * Win + iw) * C + c];
            float4 w = *(const float4*)&sW[kh * KS + kw][c];
            acc.x += fmaf(v.x, sc.x, sh.x) * w.x;
            acc.y += fmaf(v.y, sc.y, sh.y) * w.y;
            acc.z += fmaf(v.z, sc.z, sh.z) * w.z;
            acc.w += fmaf(v.w, sc.w, sh.w) * w.w;
        }
    }
    *(float4*)&out[(((size_t)b * Hout + oh) * Wout + ow) * C + c] = acc;
}

// ---------------- channel mixer GEMM: bf16x3 tensor-core --------------------
template<int MODE>
__global__ __launch_bounds__(256) void mix_mma_kernel(
    const float* __restrict__ X, const float* __restrict__ Wt,
    const float* __restrict__ bias, float* __restrict__ Y,
    float* __restrict__ sums, int M, int N, int K, int spatial)
{
    constexpr int BM = 128, BN = 128, BK = 32;
    constexpr int LDA = BK / 2 + 4;
    __shared__ unsigned As_h[BM][LDA], As_l[BM][LDA];
    __shared__ unsigned Bs_h[BN][LDA], Bs_l[BN][LDA];
    __shared__ float sSum[BN], sSq[BN];

    const int tid  = threadIdx.x;
    const int wid  = tid >> 5, lane = tid & 31;
    const int g    = lane >> 2, tig = lane & 3;
    const int wm   = (wid >> 2) * 64;
    const int wn   = (wid & 3) * 32;
    const int m0   = blockIdx.x * BM, n0 = blockIdx.y * BN;

    if (MODE == 0) {
        for (int i = tid; i < BN; i += 256) { sSum[i] = 0.f; sSq[i] = 0.f; }
    }

    float acc[4][4][4];
#pragma unroll
    for (int mi = 0; mi < 4; mi++)
#pragma unroll
        for (int ni = 0; ni < 4; ni++)
#pragma unroll
            for (int r = 0; r < 4; r++) acc[mi][ni][r] = 0.f;

    const float* Xp = X + (size_t)m0 * K;
    const float* Wp = Wt + n0;

    float4 xa[4], wb[4];
#pragma unroll
    for (int v = 0; v < 4; v++) {
        int idx = tid + 256 * v;
        int m = idx >> 3, q = idx & 7;
        xa[v] = *(const float4*)(Xp + (size_t)m * K + q * 4);
    }
#pragma unroll
    for (int v = 0; v < 2; v++) {
        int idx = tid + 256 * v;
        int j = idx >> 5, nc = idx & 31;
        wb[2 * v]     = *(const float4*)(Wp + (size_t)(2 * j) * N + 4 * nc);
        wb[2 * v + 1] = *(const float4*)(Wp + (size_t)(2 * j + 1) * N + 4 * nc);
    }

    const int nk = K / BK;
    for (int kt = 0; kt < nk; kt++) {
        if (kt > 0) __syncthreads();
#pragma unroll
        for (int v = 0; v < 4; v++) {
            int idx = tid + 256 * v;
            int m = idx >> 3, q = idx & 7;
            unsigned h0, l0, h1, l1;
            split_pack(xa[v].x, xa[v].y, h0, l0);
            split_pack(xa[v].z, xa[v].w, h1, l1);
            As_h[m][2 * q] = h0; As_h[m][2 * q + 1] = h1;
            As_l[m][2 * q] = l0; As_l[m][2 * q + 1] = l1;
        }
#pragma unroll
        for (int v = 0; v < 2; v++) {
            int idx = tid + 256 * v;
            int j = idx >> 5, nc = idx & 31;
            float4 f0 = wb[2 * v], f1 = wb[2 * v + 1];
            unsigned h, l;
            split_pack(f0.x, f1.x, h, l); Bs_h[4 * nc + 0][j] = h; Bs_l[4 * nc + 0][j] = l;
            split_pack(f0.y, f1.y, h, l); Bs_h[4 * nc + 1][j] = h; Bs_l[4 * nc + 1][j] = l;
            split_pack(f0.z, f1.z, h, l); Bs_h[4 * nc + 2][j] = h; Bs_l[4 * nc + 2][j] = l;
            split_pack(f0.w, f1.w, h, l); Bs_h[4 * nc + 3][j] = h; Bs_l[4 * nc + 3][j] = l;
        }
        __syncthreads();

        if (kt + 1 < nk) {
            const float* Xn = Xp + (kt + 1) * BK;
            const float* Wn = Wp + (size_t)(kt + 1) * BK * N;
#pragma unroll
            for (int v = 0; v < 4; v++) {
                int idx = tid + 256 * v;
                int m = idx >> 3, q = idx & 7;
                xa[v] = *(const float4*)(Xn + (size_t)m * K + q * 4);
            }
#pragma unroll
            for (int v = 0; v < 2; v++) {
                int idx = tid + 256 * v;
                int j = idx >> 5, nc = idx & 31;
                wb[2 * v]     = *(const float4*)(Wn + (size_t)(2 * j) * N + 4 * nc);
                wb[2 * v + 1] = *(const float4*)(Wn + (size_t)(2 * j + 1) * N + 4 * nc);
            }
        }

#pragma unroll
        for (int s = 0; s < 2; s++) {
            unsigned ah[4][4], al[4][4], bh[4][2], bl[4][2];
#pragma unroll
            for (int mi = 0; mi < 4; mi++) {
                int r0 = wm + 16 * mi + g, r1 = r0 + 8;
                int c0 = 8 * s + tig;
                ah[mi][0] = As_h[r0][c0];     ah[mi][1] = As_h[r1][c0];
                ah[mi][2] = As_h[r0][c0 + 4]; ah[mi][3] = As_h[r1][c0 + 4];
                al[mi][0] = As_l[r0][c0];     al[mi][1] = As_l[r1][c0];
                al[mi][2] = As_l[r0][c0 + 4]; al[mi][3] = As_l[r1][c0 + 4];
            }
#pragma unroll
            for (int ni = 0; ni < 4; ni++) {
                int n = wn + 8 * ni + g;
                int c0 = 8 * s + tig;
                bh[ni][0] = Bs_h[n][c0]; bh[ni][1] = Bs_h[n][c0 + 4];
                bl[ni][0] = Bs_l[n][c0]; bl[ni][1] = Bs_l[n][c0 + 4];
            }
#pragma unroll
            for (int mi = 0; mi < 4; mi++)
#pragma unroll
                for (int ni = 0; ni < 4; ni++) {
                    mma_bf16(acc[mi][ni], ah[mi][0], ah[mi][1], ah[mi][2], ah[mi][3],
                             bh[ni][0], bh[ni][1]);
                    mma_bf16(acc[mi][ni], ah[mi][0], ah[mi][1], ah[mi][2], ah[mi][3],
                             bl[ni][0], bl[ni][1]);
                    mma_bf16(acc[mi][ni], al[mi][0], al[mi][1], al[mi][2], al[mi][3],
                             bh[ni][0], bh[ni][1]);
                }
        }
    }

    float2 bv[4];
#pragma unroll
    for (int ni = 0; ni < 4; ni++)
        bv[ni] = *(const float2*)(bias + n0 + wn + 8 * ni + 2 * tig);

    if (MODE == 0) {
        float cs[4][2], cq[4][2];
#pragma unroll
        for (int ni = 0; ni < 4; ni++) { cs[ni][0] = cs[ni][1] = 0.f; cq[ni][0] = cq[ni][1] = 0.f; }
#pragma unroll
        for (int mi = 0; mi < 4; mi++) {
            int r0 = m0 + wm + 16 * mi + g, r1 = r0 + 8;
#pragma unroll
            for (int ni = 0; ni < 4; ni++) {
                int n = n0 + wn + 8 * ni + 2 * tig;
                float v0 = acc[mi][ni][0] + bv[ni].x;
                float v1 = acc[mi][ni][1] + bv[ni].y;
                float v2 = acc[mi][ni][2] + bv[ni].x;
                float v3 = acc[mi][ni][3] + bv[ni].y;
                v0 = v0 > 0.f ? v0 : 0.2f * v0;
                v1 = v1 > 0.f ? v1 : 0.2f * v1;
                v2 = v2 > 0.f ? v2 : 0.2f * v2;
                v3 = v3 > 0.f ? v3 : 0.2f * v3;
                *(float2*)(Y + (size_t)r0 * N + n) = make_float2(v0, v1);
                *(float2*)(Y + (size_t)r1 * N + n) = make_float2(v2, v3);
                cs[ni][0] += v0 + v2; cs[ni][1] += v1 + v3;
                cq[ni][0] += v0 * v0 + v2 * v2; cq[ni][1] += v1 * v1 + v3 * v3;
            }
        }
#pragma unroll
        for (int ni = 0; ni < 4; ni++) {
            int n = wn + 8 * ni + 2 * tig;
            atomicAdd(&sSum[n],     cs[ni][0]);
            atomicAdd(&sSum[n + 1], cs[ni][1]);
            atomicAdd(&sSq[n],      cq[ni][0]);
            atomicAdd(&sSq[n + 1],  cq[ni][1]);
        }
        __syncthreads();
        for (int i = tid; i < BN; i += 256) {
            atomicAdd(&sums[n0 + i],     sSum[i]);
            atomicAdd(&sums[N + n0 + i], sSq[i]);
        }
    } else {
#pragma unroll
        for (int mi = 0; mi < 4; mi++) {
            int r0 = m0 + wm + 16 * mi + g, r1 = r0 + 8;
            int b0i = r0 / spatial, p0 = r0 % spatial;
            int b1i = r1 / spatial, p1 = r1 % spatial;
#pragma unroll
            for (int ni = 0; ni < 4; ni++) {
                int n = n0 + wn + 8 * ni + 2 * tig;
                float v0 = acc[mi][ni][0] + bv[ni].x;
                float v1 = acc[mi][ni][1] + bv[ni].y;
                float v2 = acc[mi][ni][2] + bv[ni].x;
                float v3 = acc[mi][ni][3] + bv[ni].y;
                v0 = 1.f / (1.f + expf(-v0));
                v1 = 1.f / (1.f + expf(-v1));
                v2 = 1.f / (1.f + expf(-v2));
                v3 = 1.f / (1.f + expf(-v3));
                Y[((size_t)b0i * N + n)     * spatial + p0] = v0;
                Y[((size_t)b0i * N + n + 1) * spatial + p0] = v1;
                Y[((size_t)b1i * N + n)     * spatial + p1] = v2;
                Y[((size_t)b1i * N + n + 1) * spatial + p1] = v3;
            }
        }
    }
}

__global__ void write_label_kernel(const int* __restrict__ label, float* __restrict__ out, int n)
{
    int i = threadIdx.x;
    if (i < n) out[i] = (float)label[i];
}

// ---------------- launcher ---------------------------------------------------
extern "C" void kernel_launch(void* const* d_in, const int* in_sizes, int n_in,
                              void* d_out, int out_size)
{
    const float* input = (const float*)d_in[0];
    const int*   label = (const int*)d_in[1];
    const float* emb   = (const float*)d_in[2];
    const float* lw[5] = {(const float*)d_in[3], (const float*)d_in[5], (const float*)d_in[7],
                          (const float*)d_in[9], (const float*)d_in[11]};
    const float* lb[5] = {(const float*)d_in[4], (const float*)d_in[6], (const float*)d_in[8],
                          (const float*)d_in[10], (const float*)d_in[12]};
    const float* cmw[5] = {(const float*)d_in[13], (const float*)d_in[15], (const float*)d_in[17],
                           (const float*)d_in[19], (const float*)d_in[21]};
    const float* cmb[5] = {(const float*)d_in[14], (const float*)d_in[16], (const float*)d_in[18],
                           (const float*)d_in[20], (const float*)d_in[22]};
    const float* bng[4] = {(const float*)d_in[23], (const float*)d_in[25],
                           (const float*)d_in[27], (const float*)d_in[29]};
    const float* bnb[4] = {(const float*)d_in[24], (const float*)d_in[26],
                           (const float*)d_in[28], (const float*)d_in[30]};

    float *pA, *pB, *pDw, *pK, *pSums;
    cudaGetSymbolAddress((void**)&pA,    g_bufA);
    cudaGetSymbolAddress((void**)&pB,    g_bufB);
    cudaGetSymbolAddress((void**)&pDw,   g_dw);
    cudaGetSymbolAddress((void**)&pK,    g_kern);
    cudaGetSymbolAddress((void**)&pSums, g_sums);

    float* out = (float*)d_out;

    // ---------- prep: all dyn kernels + zero all sums ----------
    prep_kernel<<<dim3(33, 128), 256>>>(label, emb, lw[0], lb[0], lw[1], lb[1],
                                        lw[2], lb[2], lw[3], lb[3], lw[4], lb[4],
                                        pK, pSums);

    // ---------- Layer 1 (fused): dwconv(3ch,128->64) + mix(3->64) ----------
    l1_fused_kernel<<<dim3(64, 128), 256>>>(input, pK + KOFF1, cmw[0], cmb[0], pA, pSums + SOFF1);

    // ---------- Layer 2: dwconv(64ch,64->32,k4) [bn1 folded] + mix(64->128) ----------
    {
        dwconv_v2_kernel<4, 64, 64, 64, 32, 32, 2, 1><<<dim3(32, 128), 16 * 32>>>(
            pA, pSums + SOFF1, bng[0], bnb[0], 1.f / (float)(128 * 64 * 64), pK + KOFF2, pDw);
        int M = 128 * 32 * 32, N = 128, K = 64;
        mix_mma_kernel<0><<<dim3(M / 128, N / 128), 256>>>(
            pDw, cmw[1], cmb[1], pB, pSums + SOFF2, M, N, K, 0);
    }
    // ---------- Layer 3: dwconv(128ch,32->16,k3) [bn2 folded] + mix(128->256) ----------
    {
        dwconv_v2_kernel<3, 128, 32, 32, 16, 16, 2, 1><<<dim3(16, 128), 32 * 16>>>(
            pB, pSums + SOFF2, bng[1], bnb[1], 1.f / (float)(128 * 32 * 32), pK + KOFF3, pDw);
        int M = 128 * 16 * 16, N = 256, K = 128;
        mix_mma_kernel<0><<<dim3(M / 128, N / 128), 256>>>(
            pDw, cmw[2], cmb[2], pA, pSums + SOFF3, M, N, K, 0);
    }
    // ---------- Layer 4: dwconv(256ch,16->8,k4) [bn3 folded] + mix(256->512) ----------
    {
        dwconv_v2_kernel<4, 256, 16, 16, 8, 8, 2, 1><<<dim3(8, 128), 64 * 8>>>(
            pA, pSums + SOFF3, bng[2], bnb[2], 1.f / (float)(128 * 16 * 16), pK + KOFF4, pDw);
        int M = 128 * 8 * 8, N = 512, K = 256;
        mix_mma_kernel<0><<<dim3(M / 128, N / 128), 256>>>(
            pDw, cmw[3], cmb[3], pB, pSums + SOFF4, M, N, K, 0);
    }
    // ---------- Layer 5: dwconv(512ch,8->7,k2) [bn4 folded] + mix(512->512)+sigmoid ----------
    {
        dwconv_v2_kernel<2, 512, 8, 8, 7, 7, 1, 0><<<dim3(7, 128), 128 * 7>>>(
            pB, pSums + SOFF4, bng[3], bnb[3], 1.f / (float)(128 * 8 * 8), pK + KOFF5, pDw);
        int M = 128 * 49, N = 512, K = 512;
        mix_mma_kernel<1><<<dim3(M / 128, N / 128), 256>>>(
            pDw, cmw[4], cmb[4], out, nullptr, M, N, K, 49);
    }
    // ---------- label tail (if output concatenates (z, label)) ----------
    {
        long long zElems = 128LL * 512 * 49;
        long long tail = (long long)out_size - zElems;
        if (tail > 0) {
            int n = tail > 128 ? 128 : (int)tail;
            write_label_kernel<<<1, 128>>>(label, out + zElems, n);
        }
    }
}

// round 5
// speedup vs baseline: 2.4737x; 1.2060x over previous
#include <cuda_runtime.h>
#include <cuda_bf16.h>
#include <cstddef>

// ---------------- scratch (device globals; no allocation allowed) ----------
__device__ float g_bufA[33554432];                // mix outputs fp32 (NHWC)
__device__ float g_bufB[16777216];                // mix outputs fp32 (NHWC)
__device__ __nv_bfloat16 g_dwH[8388608];          // dwconv out hi plane (M x K)
__device__ __nv_bfloat16 g_dwL[8388608];          // dwconv out lo plane
__device__ __nv_bfloat16 g_wspH[434176];          // split mixer weights hi (N x K)
__device__ __nv_bfloat16 g_wspL[434176];          // split mixer weights lo
__device__ float g_kern[1179648];                 // all 5 dyn kernel sets
__device__ float g_sums[2048];                    // per-layer sum/sumsq regions

// dyn-kernel region offsets (floats)
#define KOFF1 0
#define KOFF2 6144
#define KOFF3 137216
#define KOFF4 284672
#define KOFF5 808960
// BN sums region offsets
#define SOFF1 0
#define SOFF2 128
#define SOFF3 384
#define SOFF4 896
// split-weight region offsets (elements, N x K layout)
#define W2OFF 0
#define W3OFF 8192
#define W4OFF 40960
#define W5OFF 172032

// ---------------- helpers ----------------------------------------------------
__device__ __forceinline__ void split1(float v, __nv_bfloat16& h, __nv_bfloat16& l)
{
    h = __float2bfloat16(v);
    l = __float2bfloat16(v - __bfloat162float(h));
}

__device__ __forceinline__ void mma_bf16(float* c, unsigned a0, unsigned a1, unsigned a2,
                                         unsigned a3, unsigned b0, unsigned b1)
{
    asm volatile(
        "mma.sync.aligned.m16n8k16.row.col.f32.bf16.bf16.f32 "
        "{%0,%1,%2,%3}, {%4,%5,%6,%7}, {%8,%9}, {%0,%1,%2,%3};\n"
        : "+f"(c[0]), "+f"(c[1]), "+f"(c[2]), "+f"(c[3])
        : "r"(a0), "r"(a1), "r"(a2), "r"(a3), "r"(b0), "r"(b1));
}

__device__ __forceinline__ void cp16(void* dst, const void* src)
{
    unsigned d = (unsigned)__cvta_generic_to_shared(dst);
    asm volatile("cp.async.cg.shared.global [%0], [%1], 16;\n" :: "r"(d), "l"(src));
}
#define CP_COMMIT() asm volatile("cp.async.commit_group;\n" ::: "memory")
#define CP_WAIT(n)  asm volatile("cp.async.wait_group %0;\n" :: "n"(n) : "memory")

// ---------------- prep: all dyn kernels (tanh(e@W+b)) + zero sums -----------
__global__ void prep_kernel(const int* __restrict__ label, const float* __restrict__ emb,
                            const float* __restrict__ w1, const float* __restrict__ b1,
                            const float* __restrict__ w2, const float* __restrict__ b2,
                            const float* __restrict__ w3, const float* __restrict__ b3,
                            const float* __restrict__ w4, const float* __restrict__ b4,
                            const float* __restrict__ w5, const float* __restrict__ b5,
                            float* __restrict__ kern, float* __restrict__ sums)
{
    int b = blockIdx.y;
    int i = blockIdx.x * 256 + threadIdx.x;
    if (b == 0 && i < 1920) sums[i] = 0.f;

    const float* W; const float* bb; int ck, off, j;
    if (i < 48)            { W = w1; bb = b1; ck = 48;   off = KOFF1; j = i; }
    else if (i < 1072)     { W = w2; bb = b2; ck = 1024; off = KOFF2; j = i - 48; }
    else if (i < 2224)     { W = w3; bb = b3; ck = 1152; off = KOFF3; j = i - 1072; }
    else if (i < 6320)     { W = w4; bb = b4; ck = 4096; off = KOFF4; j = i - 2224; }
    else if (i < 8368)     { W = w5; bb = b5; ck = 2048; off = KOFF5; j = i - 6320; }
    else return;

    const float* e = emb + label[b] * 5;
    float a = bb[j];
#pragma unroll
    for (int t = 0; t < 5; t++) a += e[t] * W[t * ck + j];
    kern[off + (size_t)b * ck + j] = tanhf(a);
}

// ---------------- wsplit: mixer weights fp32 (K x N) -> bf16 hi/lo (N x K) --
__global__ void wsplit_kernel(const float* __restrict__ w2, const float* __restrict__ w3,
                              const float* __restrict__ w4, const float* __restrict__ w5,
                              __nv_bfloat16* __restrict__ wh, __nv_bfloat16* __restrict__ wl)
{
    int i = blockIdx.x * 256 + threadIdx.x;
    const float* W; int K, N, off, j;
    if (i < 8192)        { W = w2; K = 64;  N = 128; off = W2OFF; j = i; }
    else if (i < 40960)  { W = w3; K = 128; N = 256; off = W3OFF; j = i - 8192; }
    else if (i < 172032) { W = w4; K = 256; N = 512; off = W4OFF; j = i - 40960; }
    else if (i < 434176) { W = w5; K = 512; N = 512; off = W5OFF; j = i - 172032; }
    else return;
    int n = j / K, k = j % K;
    __nv_bfloat16 h, l;
    split1(W[(size_t)k * N + n], h, l);
    wh[off + j] = h;
    wl[off + j] = l;
}

// ---------------- layer 1 fused: dwconv(3ch) + mix(3->64) + lrelu + stats ---
__global__ __launch_bounds__(256) void l1_fused_kernel(
    const float* __restrict__ x, const float* __restrict__ kern,
    const float* __restrict__ W, const float* __restrict__ bias,
    float* __restrict__ Y, float* __restrict__ sums)
{
    __shared__ float sW[3][64];
    __shared__ float sB[64];
    __shared__ float sK[3][16];
    __shared__ float sD[3][64];
    __shared__ float sSum[64], sSq[64];

    int b = blockIdx.y, oh = blockIdx.x;
    int tid = threadIdx.x;

    if (tid < 192) sW[tid / 64][tid % 64] = W[tid];
    if (tid < 64) { sB[tid] = bias[tid]; sSum[tid] = 0.f; sSq[tid] = 0.f; }
    if (tid >= 192 && tid < 240) { int q = tid - 192; sK[q / 16][q % 16] = kern[(size_t)b * 48 + q]; }
    __syncthreads();

    if (tid < 192) {
        int c = tid / 64, ow = tid % 64;
        const float* xp = x + ((size_t)b * 3 + c) * 16384;
        float a = 0.f;
#pragma unroll
        for (int kh = 0; kh < 4; kh++) {
            int ih = oh * 2 - 1 + kh;
            if ((unsigned)ih < 128u) {
#pragma unroll
                for (int kw = 0; kw < 4; kw++) {
                    int iw = ow * 2 - 1 + kw;
                    if ((unsigned)iw < 128u) a += xp[ih * 128 + iw] * sK[c][kh * 4 + kw];
                }
            }
        }
        sD[c][ow] = a;
    }
    __syncthreads();

    int tx = tid & 63, py = tid >> 6;
    float w0 = sW[0][tx], w1 = sW[1][tx], w2 = sW[2][tx], bb = sB[tx];
    float s = 0.f, q = 0.f;
#pragma unroll
    for (int pix = py; pix < 64; pix += 4) {
        float v = fmaf(sD[0][pix], w0, fmaf(sD[1][pix], w1, fmaf(sD[2][pix], w2, bb)));
        v = v > 0.f ? v : 0.2f * v;
        Y[(((size_t)b * 64 + oh) * 64 + pix) * 64 + tx] = v;
        s += v; q += v * v;
    }
    atomicAdd(&sSum[tx], s);
    atomicAdd(&sSq[tx], q);
    __syncthreads();
    if (tid < 64) { atomicAdd(&sums[tid], sSum[tid]); atomicAdd(&sums[64 + tid], sSq[tid]); }
}

// ---------------- dwconv v3: smem weights, float4, BN fold, split bf16 out --
template<int KS, int C, int Hin, int Win, int Hout, int Wout, int Stride, int Pad>
__global__ __launch_bounds__((C / 4) * Wout) void dwconv_v3_kernel(
    const float* __restrict__ Yin, const float* __restrict__ sums,
    const float* __restrict__ bn_g, const float* __restrict__ bn_b, float invCnt,
    const float* __restrict__ kern,
    __nv_bfloat16* __restrict__ outH, __nv_bfloat16* __restrict__ outL)
{
    constexpr int KK = KS * KS;
    constexpr int CG = C / 4;
    constexpr int NT = CG * Wout;
    __shared__ __align__(16) float sW[KK][C];
    __shared__ __align__(16) float sSc[C], sSh[C];

    const int b = blockIdx.y, oh = blockIdx.x;
    const int tid = threadIdx.x;

    for (int c = tid; c < C; c += NT) {
        float mean = sums[c] * invCnt;
        float var  = sums[C + c] * invCnt - mean * mean;
        float sc = bn_g[c] * rsqrtf(var + 1e-5f);
        sSc[c] = sc;
        sSh[c] = bn_b[c] - mean * sc;
    }
    const float* kb = kern + (size_t)b * C * KK;
    for (int idx = tid; idx < C * KK; idx += NT) {
        int c = idx / KK, tap = idx % KK;
        sW[tap][c] = kb[idx];
    }
    __syncthreads();

    const int cg = tid % CG, ow = tid / CG;
    const int c = cg * 4;
    const float4 sc = *(const float4*)&sSc[c];
    const float4 sh = *(const float4*)&sSh[c];

    float4 acc = make_float4(0.f, 0.f, 0.f, 0.f);
#pragma unroll
    for (int kh = 0; kh < KS; kh++) {
        int ih = oh * Stride - Pad + kh;
        if ((unsigned)ih >= (unsigned)Hin) continue;
#pragma unroll
        for (int kw = 0; kw < KS; kw++) {
            int iw = ow * Stride - Pad + kw;
            if ((unsigned)iw >= (unsigned)Win) continue;
            float4 v = *(const float4*)&Yin[(((size_t)b * Hin + ih) * Win + iw) * C + c];
            float4 w = *(const float4*)&sW[kh * KS + kw][c];
            acc.x += fmaf(v.x, sc.x, sh.x) * w.x;
            acc.y += fmaf(v.y, sc.y, sh.y) * w.y;
            acc.z += fmaf(v.z, sc.z, sh.z) * w.z;
            acc.w += fmaf(v.w, sc.w, sh.w) * w.w;
        }
    }
    __nv_bfloat16 h0, h1, h2, h3, l0, l1, l2, l3;
    split1(acc.x, h0, l0); split1(acc.y, h1, l1);
    split1(acc.z, h2, l2); split1(acc.w, h3, l3);
    size_t o = (((size_t)b * Hout + oh) * Wout + ow) * C + c;
    uint2 hv, lv;
    hv.x = (unsigned)__bfloat16_as_ushort(h0) | ((unsigned)__bfloat16_as_ushort(h1) << 16);
    hv.y = (unsigned)__bfloat16_as_ushort(h2) | ((unsigned)__bfloat16_as_ushort(h3) << 16);
    lv.x = (unsigned)__bfloat16_as_ushort(l0) | ((unsigned)__bfloat16_as_ushort(l1) << 16);
    lv.y = (unsigned)__bfloat16_as_ushort(l2) | ((unsigned)__bfloat16_as_ushort(l3) << 16);
    *(uint2*)&outH[o] = hv;
    *(uint2*)&outL[o] = lv;
}

// ---------------- channel mixer GEMM v3: bf16x3 MMA + cp.async pipeline -----
// A (hi/lo): M x K bf16 row-major.  W (hi/lo): N x K bf16 row-major.
template<int MODE>
__global__ __launch_bounds__(256) void mix_mma3_kernel(
    const __nv_bfloat16* __restrict__ Ah, const __nv_bfloat16* __restrict__ Al,
    const __nv_bfloat16* __restrict__ Wh, const __nv_bfloat16* __restrict__ Wl,
    const float* __restrict__ bias, float* __restrict__ Y,
    float* __restrict__ sums, int M, int N, int K, int spatial)
{
    extern __shared__ unsigned smemU[];          // 2 stages x 4 arrays x 128 x 20 u32
    __shared__ float sSum[128], sSq[128];

    const int tid  = threadIdx.x;
    const int wid  = tid >> 5, lane = tid & 31;
    const int g    = lane >> 2, tig = lane & 3;
    const int wm   = (wid >> 2) * 64;
    const int wn   = (wid & 3) * 32;
    const int m0   = blockIdx.x * 128, n0 = blockIdx.y * 128;

    if (MODE == 0) {
        if (tid < 128) { sSum[tid] = 0.f; sSq[tid] = 0.f; }
    }

    float acc[4][4][4];
#pragma unroll
    for (int mi = 0; mi < 4; mi++)
#pragma unroll
        for (int ni = 0; ni < 4; ni++)
#pragma unroll
            for (int r = 0; r < 4; r++) acc[mi][ni][r] = 0.f;

    auto load_stage = [&](int kt, int s) {
        unsigned* base = smemU + s * 10240;
        const int k0 = kt * 32;
#pragma unroll
        for (int v = 0; v < 8; v++) {
            int cid = tid + 256 * v;
            int arr = cid >> 9;                   // constant per v
            int r   = (cid >> 2) & 127;
            int ch  = cid & 3;
            const __nv_bfloat16* src;
            if (arr == 0)      src = Ah + (size_t)(m0 + r) * K + k0 + ch * 8;
            else if (arr == 1) src = Al + (size_t)(m0 + r) * K + k0 + ch * 8;
            else if (arr == 2) src = Wh + (size_t)(n0 + r) * K + k0 + ch * 8;
            else               src = Wl + (size_t)(n0 + r) * K + k0 + ch * 8;
            cp16(base + arr * 2560 + r * 20 + ch * 4, src);
        }
    };

    const int nk = K / 32;
    load_stage(0, 0);
    CP_COMMIT();

    for (int kt = 0; kt < nk; kt++) {
        if (kt + 1 < nk) {
            load_stage(kt + 1, (kt + 1) & 1);
            CP_COMMIT();
            CP_WAIT(1);
        } else {
            CP_WAIT(0);
        }
        __syncthreads();

        unsigned* base = smemU + (kt & 1) * 10240;
        unsigned (*As_h)[20] = (unsigned(*)[20])(base);
        unsigned (*As_l)[20] = (unsigned(*)[20])(base + 2560);
        unsigned (*Bs_h)[20] = (unsigned(*)[20])(base + 5120);
        unsigned (*Bs_l)[20] = (unsigned(*)[20])(base + 7680);

#pragma unroll
        for (int s = 0; s < 2; s++) {
            unsigned ah[4][4], al[4][4], bh[4][2], bl[4][2];
#pragma unroll
            for (int mi = 0; mi < 4; mi++) {
                int r0 = wm + 16 * mi + g, r1 = r0 + 8;
                int c0 = 8 * s + tig;
                ah[mi][0] = As_h[r0][c0];     ah[mi][1] = As_h[r1][c0];
                ah[mi][2] = As_h[r0][c0 + 4]; ah[mi][3] = As_h[r1][c0 + 4];
                al[mi][0] = As_l[r0][c0];     al[mi][1] = As_l[r1][c0];
                al[mi][2] = As_l[r0][c0 + 4]; al[mi][3] = As_l[r1][c0 + 4];
            }
#pragma unroll
            for (int ni = 0; ni < 4; ni++) {
                int n = wn + 8 * ni + g;
                int c0 = 8 * s + tig;
                bh[ni][0] = Bs_h[n][c0]; bh[ni][1] = Bs_h[n][c0 + 4];
                bl[ni][0] = Bs_l[n][c0]; bl[ni][1] = Bs_l[n][c0 + 4];
            }
#pragma unroll
            for (int mi = 0; mi < 4; mi++)
#pragma unroll
                for (int ni = 0; ni < 4; ni++) {
                    mma_bf16(acc[mi][ni], ah[mi][0], ah[mi][1], ah[mi][2], ah[mi][3],
                             bh[ni][0], bh[ni][1]);
                    mma_bf16(acc[mi][ni], ah[mi][0], ah[mi][1], ah[mi][2], ah[mi][3],
                             bl[ni][0], bl[ni][1]);
                    mma_bf16(acc[mi][ni], al[mi][0], al[mi][1], al[mi][2], al[mi][3],
                             bh[ni][0], bh[ni][1]);
                }
        }
        __syncthreads();
    }

    // ---------------- epilogue ----------------
    float2 bv[4];
#pragma unroll
    for (int ni = 0; ni < 4; ni++)
        bv[ni] = *(const float2*)(bias + n0 + wn + 8 * ni + 2 * tig);

    if (MODE == 0) {
        float cs[4][2], cq[4][2];
#pragma unroll
        for (int ni = 0; ni < 4; ni++) { cs[ni][0] = cs[ni][1] = 0.f; cq[ni][0] = cq[ni][1] = 0.f; }
#pragma unroll
        for (int mi = 0; mi < 4; mi++) {
            int r0 = m0 + wm + 16 * mi + g, r1 = r0 + 8;
#pragma unroll
            for (int ni = 0; ni < 4; ni++) {
                int n = n0 + wn + 8 * ni + 2 * tig;
                float v0 = acc[mi][ni][0] + bv[ni].x;
                float v1 = acc[mi][ni][1] + bv[ni].y;
                float v2 = acc[mi][ni][2] + bv[ni].x;
                float v3 = acc[mi][ni][3] + bv[ni].y;
                v0 = v0 > 0.f ? v0 : 0.2f * v0;
                v1 = v1 > 0.f ? v1 : 0.2f * v1;
                v2 = v2 > 0.f ? v2 : 0.2f * v2;
                v3 = v3 > 0.f ? v3 : 0.2f * v3;
                *(float2*)(Y + (size_t)r0 * N + n) = make_float2(v0, v1);
                *(float2*)(Y + (size_t)r1 * N + n) = make_float2(v2, v3);
                cs[ni][0] += v0 + v2; cs[ni][1] += v1 + v3;
                cq[ni][0] += v0 * v0 + v2 * v2; cq[ni][1] += v1 * v1 + v3 * v3;
            }
        }
#pragma unroll
        for (int ni = 0; ni < 4; ni++) {
            int n = wn + 8 * ni + 2 * tig;
            atomicAdd(&sSum[n],     cs[ni][0]);
            atomicAdd(&sSum[n + 1], cs[ni][1]);
            atomicAdd(&sSq[n],      cq[ni][0]);
            atomicAdd(&sSq[n + 1],  cq[ni][1]);
        }
        __syncthreads();
        if (tid < 128) {
            atomicAdd(&sums[n0 + tid],     sSum[tid]);
            atomicAdd(&sums[N + n0 + tid], sSq[tid]);
        }
    } else {
#pragma unroll
        for (int mi = 0; mi < 4; mi++) {
            int r0 = m0 + wm + 16 * mi + g, r1 = r0 + 8;
            int b0i = r0 / spatial, p0 = r0 % spatial;
            int b1i = r1 / spatial, p1 = r1 % spatial;
#pragma unroll
            for (int ni = 0; ni < 4; ni++) {
                int n = n0 + wn + 8 * ni + 2 * tig;
                float v0 = acc[mi][ni][0] + bv[ni].x;
                float v1 = acc[mi][ni][1] + bv[ni].y;
                float v2 = acc[mi][ni][2] + bv[ni].x;
                float v3 = acc[mi][ni][3] + bv[ni].y;
                v0 = 1.f / (1.f + expf(-v0));
                v1 = 1.f / (1.f + expf(-v1));
                v2 = 1.f / (1.f + expf(-v2));
                v3 = 1.f / (1.f + expf(-v3));
                Y[((size_t)b0i * N + n)     * spatial + p0] = v0;
                Y[((size_t)b0i * N + n + 1) * spatial + p0] = v1;
                Y[((size_t)b1i * N + n)     * spatial + p1] = v2;
                Y[((size_t)b1i * N + n + 1) * spatial + p1] = v3;
            }
        }
    }
}

__global__ void write_label_kernel(const int* __restrict__ label, float* __restrict__ out, int n)
{
    int i = threadIdx.x;
    if (i < n) out[i] = (float)label[i];
}

// ---------------- launcher ---------------------------------------------------
extern "C" void kernel_launch(void* const* d_in, const int* in_sizes, int n_in,
                              void* d_out, int out_size)
{
    const float* input = (const float*)d_in[0];
    const int*   label = (const int*)d_in[1];
    const float* emb   = (const float*)d_in[2];
    const float* lw[5] = {(const float*)d_in[3], (const float*)d_in[5], (const float*)d_in[7],
                          (const float*)d_in[9], (const float*)d_in[11]};
    const float* lb[5] = {(const float*)d_in[4], (const float*)d_in[6], (const float*)d_in[8],
                          (const float*)d_in[10], (const float*)d_in[12]};
    const float* cmw[5] = {(const float*)d_in[13], (const float*)d_in[15], (const float*)d_in[17],
                           (const float*)d_in[19], (const float*)d_in[21]};
    const float* cmb[5] = {(const float*)d_in[14], (const float*)d_in[16], (const float*)d_in[18],
                           (const float*)d_in[20], (const float*)d_in[22]};
    const float* bng[4] = {(const float*)d_in[23], (const float*)d_in[25],
                           (const float*)d_in[27], (const float*)d_in[29]};
    const float* bnb[4] = {(const float*)d_in[24], (const float*)d_in[26],
                           (const float*)d_in[28], (const float*)d_in[30]};

    float *pA, *pB, *pK, *pSums;
    __nv_bfloat16 *pDwH, *pDwL, *pWH, *pWL;
    cudaGetSymbolAddress((void**)&pA,    g_bufA);
    cudaGetSymbolAddress((void**)&pB,    g_bufB);
    cudaGetSymbolAddress((void**)&pDwH,  g_dwH);
    cudaGetSymbolAddress((void**)&pDwL,  g_dwL);
    cudaGetSymbolAddress((void**)&pWH,   g_wspH);
    cudaGetSymbolAddress((void**)&pWL,   g_wspL);
    cudaGetSymbolAddress((void**)&pK,    g_kern);
    cudaGetSymbolAddress((void**)&pSums, g_sums);

    float* out = (float*)d_out;

    const int SMEM = 81920;
    cudaFuncSetAttribute(mix_mma3_kernel<0>, cudaFuncAttributeMaxDynamicSharedMemorySize, SMEM);
    cudaFuncSetAttribute(mix_mma3_kernel<1>, cudaFuncAttributeMaxDynamicSharedMemorySize, SMEM);

    // ---------- prep: dyn kernels + zero sums; split mixer weights ----------
    prep_kernel<<<dim3(33, 128), 256>>>(label, emb, lw[0], lb[0], lw[1], lb[1],
                                        lw[2], lb[2], lw[3], lb[3], lw[4], lb[4],
                                        pK, pSums);
    wsplit_kernel<<<1696, 256>>>(cmw[1], cmw[2], cmw[3], cmw[4], pWH, pWL);

    // ---------- Layer 1 (fused): dwconv(3ch,128->64) + mix(3->64) ----------
    l1_fused_kernel<<<dim3(64, 128), 256>>>(input, pK + KOFF1, cmw[0], cmb[0], pA, pSums + SOFF1);

    // ---------- Layer 2 ----------
    {
        dwconv_v3_kernel<4, 64, 64, 64, 32, 32, 2, 1><<<dim3(32, 128), 16 * 32>>>(
            pA, pSums + SOFF1, bng[0], bnb[0], 1.f / (float)(128 * 64 * 64), pK + KOFF2, pDwH, pDwL);
        int M = 128 * 32 * 32, N = 128, K = 64;
        mix_mma3_kernel<0><<<dim3(M / 128, N / 128), 256, SMEM>>>(
            pDwH, pDwL, pWH + W2OFF, pWL + W2OFF, cmb[1], pB, pSums + SOFF2, M, N, K, 0);
    }
    // ---------- Layer 3 ----------
    {
        dwconv_v3_kernel<3, 128, 32, 32, 16, 16, 2, 1><<<dim3(16, 128), 32 * 16>>>(
            pB, pSums + SOFF2, bng[1], bnb[1], 1.f / (float)(128 * 32 * 32), pK + KOFF3, pDwH, pDwL);
        int M = 128 * 16 * 16, N = 256, K = 128;
        mix_mma3_kernel<0><<<dim3(M / 128, N / 128), 256, SMEM>>>(
            pDwH, pDwL, pWH + W3OFF, pWL + W3OFF, cmb[2], pA, pSums + SOFF3, M, N, K, 0);
    }
    // ---------- Layer 4 ----------
    {
        dwconv_v3_kernel<4, 256, 16, 16, 8, 8, 2, 1><<<dim3(8, 128), 64 * 8>>>(
            pA, pSums + SOFF3, bng[2], bnb[2], 1.f / (float)(128 * 16 * 16), pK + KOFF4, pDwH, pDwL);
        int M = 128 * 8 * 8, N = 512, K = 256;
        mix_mma3_kernel<0><<<dim3(M / 128, N / 128), 256, SMEM>>>(
            pDwH, pDwL, pWH + W4OFF, pWL + W4OFF, cmb[3], pB, pSums + SOFF4, M, N, K, 0);
    }
    // ---------- Layer 5 ----------
    {
        dwconv_v3_kernel<2, 512, 8, 8, 7, 7, 1, 0><<<dim3(7, 128), 128 * 7>>>(
            pB, pSums + SOFF4, bng[3], bnb[3], 1.f / (float)(128 * 8 * 8), pK + KOFF5, pDwH, pDwL);
        int M = 128 * 49, N = 512, K = 512;
        mix_mma3_kernel<1><<<dim3(M / 128, N / 128), 256, SMEM>>>(
            pDwH, pDwL, pWH + W5OFF, pWL + W5OFF, cmb[4], out, nullptr, M, N, K, 49);
    }
    // ---------- label tail ----------
    {
        long long zElems = 128LL * 512 * 49;
        long long tail = (long long)out_size - zElems;
        if (tail > 0) {
            int n = tail > 128 ? 128 : (int)tail;
            write_label_kernel<<<1, 128>>>(label, out + zElems, n);
        }
    }
}

// round 7
// speedup vs baseline: 2.6720x; 1.0801x over previous
#include <cuda_runtime.h>
#include <cuda_bf16.h>
#include <cstddef>

// ---------------- scratch (device globals; no allocation allowed) ----------
__device__ float g_bufA[33554432];                // mix outputs fp32 (NHWC)
__device__ float g_bufB[16777216];                // mix outputs fp32 (NHWC)
__device__ __nv_bfloat16 g_dwH[8388608];          // dwconv out hi plane (M x K)
__device__ __nv_bfloat16 g_dwL[8388608];          // dwconv out lo plane
__device__ __nv_bfloat16 g_wspH[434176];          // split mixer weights hi (N x K)
__device__ __nv_bfloat16 g_wspL[434176];          // split mixer weights lo
__device__ float g_kern[1179648];                 // all 5 dyn kernel sets
__device__ float g_sums[2048];                    // per-layer sum/sumsq regions

// dyn-kernel region offsets (floats)
#define KOFF1 0
#define KOFF2 6144
#define KOFF3 137216
#define KOFF4 284672
#define KOFF5 808960
// BN sums region offsets
#define SOFF1 0
#define SOFF2 128
#define SOFF3 384
#define SOFF4 896
// split-weight region offsets (elements, N x K layout)
#define W2OFF 0
#define W3OFF 8192
#define W4OFF 40960
#define W5OFF 172032

// ---------------- helpers ----------------------------------------------------
__device__ __forceinline__ void split1(float v, __nv_bfloat16& h, __nv_bfloat16& l)
{
    h = __float2bfloat16(v);
    l = __float2bfloat16(v - __bfloat162float(h));
}

__device__ __forceinline__ void mma_bf16(float* c, unsigned a0, unsigned a1, unsigned a2,
                                         unsigned a3, unsigned b0, unsigned b1)
{
    asm volatile(
        "mma.sync.aligned.m16n8k16.row.col.f32.bf16.bf16.f32 "
        "{%0,%1,%2,%3}, {%4,%5,%6,%7}, {%8,%9}, {%0,%1,%2,%3};\n"
        : "+f"(c[0]), "+f"(c[1]), "+f"(c[2]), "+f"(c[3])
        : "r"(a0), "r"(a1), "r"(a2), "r"(a3), "r"(b0), "r"(b1));
}

__device__ __forceinline__ void cp16(void* dst, const void* src)
{
    unsigned d = (unsigned)__cvta_generic_to_shared(dst);
    asm volatile("cp.async.cg.shared.global [%0], [%1], 16;\n" :: "r"(d), "l"(src));
}
#define CP_COMMIT() asm volatile("cp.async.commit_group;\n" ::: "memory")
#define CP_WAIT(n)  asm volatile("cp.async.wait_group %0;\n" :: "n"(n) : "memory")

// ---------------- prep: all dyn kernels (tanh(e@W+b)) + zero sums -----------
__global__ void prep_kernel(const int* __restrict__ label, const float* __restrict__ emb,
                            const float* __restrict__ w1, const float* __restrict__ b1,
                            const float* __restrict__ w2, const float* __restrict__ b2,
                            const float* __restrict__ w3, const float* __restrict__ b3,
                            const float* __restrict__ w4, const float* __restrict__ b4,
                            const float* __restrict__ w5, const float* __restrict__ b5,
                            float* __restrict__ kern, float* __restrict__ sums)
{
    int b = blockIdx.y;
    int i = blockIdx.x * 256 + threadIdx.x;
    if (b == 0 && i < 1920) sums[i] = 0.f;

    const float* W; const float* bb; int ck, off, j;
    if (i < 48)            { W = w1; bb = b1; ck = 48;   off = KOFF1; j = i; }
    else if (i < 1072)     { W = w2; bb = b2; ck = 1024; off = KOFF2; j = i - 48; }
    else if (i < 2224)     { W = w3; bb = b3; ck = 1152; off = KOFF3; j = i - 1072; }
    else if (i < 6320)     { W = w4; bb = b4; ck = 4096; off = KOFF4; j = i - 2224; }
    else if (i < 8368)     { W = w5; bb = b5; ck = 2048; off = KOFF5; j = i - 6320; }
    else return;

    const float* e = emb + label[b] * 5;
    float a = bb[j];
#pragma unroll
    for (int t = 0; t < 5; t++) a += e[t] * W[t * ck + j];
    kern[off + (size_t)b * ck + j] = tanhf(a);
}

// ---------------- wsplit: mixer weights fp32 (K x N) -> bf16 hi/lo (N x K) --
__global__ void wsplit_kernel(const float* __restrict__ w2, const float* __restrict__ w3,
                              const float* __restrict__ w4, const float* __restrict__ w5,
                              __nv_bfloat16* __restrict__ wh, __nv_bfloat16* __restrict__ wl)
{
    int i = blockIdx.x * 256 + threadIdx.x;
    const float* W; int K, N, off, j;
    if (i < 8192)        { W = w2; K = 64;  N = 128; off = W2OFF; j = i; }
    else if (i < 40960)  { W = w3; K = 128; N = 256; off = W3OFF; j = i - 8192; }
    else if (i < 172032) { W = w4; K = 256; N = 512; off = W4OFF; j = i - 40960; }
    else if (i < 434176) { W = w5; K = 512; N = 512; off = W5OFF; j = i - 172032; }
    else return;
    int n = j / K, k = j % K;
    __nv_bfloat16 h, l;
    split1(W[(size_t)k * N + n], h, l);
    wh[off + j] = h;
    wl[off + j] = l;
}

// ---------------- layer 1 fused: dwconv(3ch) + mix(3->64) + lrelu + stats ---
__global__ __launch_bounds__(256) void l1_fused_kernel(
    const float* __restrict__ x, const float* __restrict__ kern,
    const float* __restrict__ W, const float* __restrict__ bias,
    float* __restrict__ Y, float* __restrict__ sums)
{
    __shared__ float sW[3][64];
    __shared__ float sB[64];
    __shared__ float sK[3][16];
    __shared__ float sD[3][64];
    __shared__ float sSum[64], sSq[64];

    int b = blockIdx.y, oh = blockIdx.x;
    int tid = threadIdx.x;

    if (tid < 192) sW[tid / 64][tid % 64] = W[tid];
    if (tid < 64) { sB[tid] = bias[tid]; sSum[tid] = 0.f; sSq[tid] = 0.f; }
    if (tid >= 192 && tid < 240) { int q = tid - 192; sK[q / 16][q % 16] = kern[(size_t)b * 48 + q]; }
    __syncthreads();

    if (tid < 192) {
        int c = tid / 64, ow = tid % 64;
        const float* xp = x + ((size_t)b * 3 + c) * 16384;
        float a = 0.f;
#pragma unroll
        for (int kh = 0; kh < 4; kh++) {
            int ih = oh * 2 - 1 + kh;
            if ((unsigned)ih < 128u) {
#pragma unroll
                for (int kw = 0; kw < 4; kw++) {
                    int iw = ow * 2 - 1 + kw;
                    if ((unsigned)iw < 128u) a += xp[ih * 128 + iw] * sK[c][kh * 4 + kw];
                }
            }
        }
        sD[c][ow] = a;
    }
    __syncthreads();

    int tx = tid & 63, py = tid >> 6;
    float w0 = sW[0][tx], w1 = sW[1][tx], w2 = sW[2][tx], bb = sB[tx];
    float s = 0.f, q = 0.f;
#pragma unroll
    for (int pix = py; pix < 64; pix += 4) {
        float v = fmaf(sD[0][pix], w0, fmaf(sD[1][pix], w1, fmaf(sD[2][pix], w2, bb)));
        v = v > 0.f ? v : 0.2f * v;
        Y[(((size_t)b * 64 + oh) * 64 + pix) * 64 + tx] = v;
        s += v; q += v * v;
    }
    atomicAdd(&sSum[tx], s);
    atomicAdd(&sSq[tx], q);
    __syncthreads();
    if (tid < 64) { atomicAdd(&sums[tid], sSum[tid]); atomicAdd(&sums[64 + tid], sSq[tid]); }
}

// ---------------- dwconv v4: 2x2 output register blocking, BN fold ----------
// Grid: (ceil(Hout/2), B). Threads: (Wout2) x (C/4). Each thread: 2x2 outputs.
template<int KS, int C, int Hin, int Win, int Hout, int Wout, int Stride, int Pad>
__global__ __launch_bounds__((C / 4) * ((Wout + 1) / 2)) void dwconv_v4_kernel(
    const float* __restrict__ Yin, const float* __restrict__ sums,
    const float* __restrict__ bn_g, const float* __restrict__ bn_b, float invCnt,
    const float* __restrict__ kern,
    __nv_bfloat16* __restrict__ outH, __nv_bfloat16* __restrict__ outL)
{
    constexpr int KK = KS * KS;
    constexpr int CG = C / 4;
    constexpr int W2 = (Wout + 1) / 2;
    constexpr int NT = CG * W2;
    constexpr int SPAN = KS + Stride;            // input span covering 2 outputs
    __shared__ __align__(16) float sW[KK][C];
    __shared__ __align__(16) float sSc[C], sSh[C];

    const int b = blockIdx.y, rp = blockIdx.x;
    const int tid = threadIdx.x;

    for (int c = tid; c < C; c += NT) {
        float mean = sums[c] * invCnt;
        float var  = sums[C + c] * invCnt - mean * mean;
        float sc = bn_g[c] * rsqrtf(var + 1e-5f);
        sSc[c] = sc;
        sSh[c] = bn_b[c] - mean * sc;
    }
    const float* kb = kern + (size_t)b * C * KK;
    for (int idx = tid; idx < C * KK; idx += NT) {
        int c = idx / KK, tap = idx % KK;
        sW[tap][c] = kb[idx];
    }
    __syncthreads();

    const int cg = tid % CG, wq = tid / CG;
    const int c = cg * 4;
    const int oh0 = 2 * rp, ow0 = 2 * wq;
    const int ihB = oh0 * Stride - Pad;
    const int iwB = ow0 * Stride - Pad;
    const float4 sc = *(const float4*)&sSc[c];
    const float4 sh = *(const float4*)&sSh[c];

    float4 acc[2][2];
#pragma unroll
    for (int oy = 0; oy < 2; oy++)
#pragma unroll
        for (int ox = 0; ox < 2; ox++) acc[oy][ox] = make_float4(0.f, 0.f, 0.f, 0.f);

#pragma unroll
    for (int rr = 0; rr < SPAN; rr++) {
        int ih = ihB + rr;
        if ((unsigned)ih >= (unsigned)Hin) continue;
        float4 v[SPAN];
#pragma unroll
        for (int cc = 0; cc < SPAN; cc++) {
            int iw = iwB + cc;
            if ((unsigned)iw < (unsigned)Win) {
                float4 raw = *(const float4*)&Yin[(((size_t)b * Hin + ih) * Win + iw) * C + c];
                v[cc].x = fmaf(raw.x, sc.x, sh.x);
                v[cc].y = fmaf(raw.y, sc.y, sh.y);
                v[cc].z = fmaf(raw.z, sc.z, sh.z);
                v[cc].w = fmaf(raw.w, sc.w, sh.w);
            } else {
                v[cc] = make_float4(0.f, 0.f, 0.f, 0.f);
            }
        }
#pragma unroll
        for (int oy = 0; oy < 2; oy++) {
            int kh = rr - oy * Stride;
            if (kh < 0 || kh >= KS) continue;
#pragma unroll
            for (int kw = 0; kw < KS; kw++) {
                float4 w = *(const float4*)&sW[kh * KS + kw][c];
#pragma unroll
                for (int ox = 0; ox < 2; ox++) {
                    float4 vv = v[kw + ox * Stride];
                    acc[oy][ox].x += vv.x * w.x;
                    acc[oy][ox].y += vv.y * w.y;
                    acc[oy][ox].z += vv.z * w.z;
                    acc[oy][ox].w += vv.w * w.w;
                }
            }
        }
    }

#pragma unroll
    for (int oy = 0; oy < 2; oy++) {
        int oh = oh0 + oy;
        if (oh >= Hout) break;
#pragma unroll
        for (int ox = 0; ox < 2; ox++) {
            int ow = ow0 + ox;
            if (ow >= Wout) break;
            float4 a = acc[oy][ox];
            __nv_bfloat16 h0, h1, h2, h3, l0, l1, l2, l3;
            split1(a.x, h0, l0); split1(a.y, h1, l1);
            split1(a.z, h2, l2); split1(a.w, h3, l3);
            size_t o = (((size_t)b * Hout + oh) * Wout + ow) * C + c;
            uint2 hv, lv;
            hv.x = (unsigned)__bfloat16_as_ushort(h0) | ((unsigned)__bfloat16_as_ushort(h1) << 16);
            hv.y = (unsigned)__bfloat16_as_ushort(h2) | ((unsigned)__bfloat16_as_ushort(h3) << 16);
            lv.x = (unsigned)__bfloat16_as_ushort(l0) | ((unsigned)__bfloat16_as_ushort(l1) << 16);
            lv.y = (unsigned)__bfloat16_as_ushort(l2) | ((unsigned)__bfloat16_as_ushort(l3) << 16);
            *(uint2*)&outH[o] = hv;
            *(uint2*)&outL[o] = lv;
        }
    }
}

// ---------------- channel mixer GEMM v3: bf16x3 MMA + cp.async pipeline -----
template<int MODE>
__global__ __launch_bounds__(256) void mix_mma3_kernel(
    const __nv_bfloat16* __restrict__ Ah, const __nv_bfloat16* __restrict__ Al,
    const __nv_bfloat16* __restrict__ Wh, const __nv_bfloat16* __restrict__ Wl,
    const float* __restrict__ bias, float* __restrict__ Y,
    float* __restrict__ sums, int M, int N, int K, int spatial)
{
    extern __shared__ unsigned smemU[];          // 2 stages x 4 arrays x 128 x 20 u32
    __shared__ float sSum[128], sSq[128];

    const int tid  = threadIdx.x;
    const int wid  = tid >> 5, lane = tid & 31;
    const int g    = lane >> 2, tig = lane & 3;
    const int wm   = (wid >> 2) * 64;
    const int wn   = (wid & 3) * 32;
    const int m0   = blockIdx.x * 128, n0 = blockIdx.y * 128;

    if (MODE == 0) {
        if (tid < 128) { sSum[tid] = 0.f; sSq[tid] = 0.f; }
    }

    float acc[4][4][4];
#pragma unroll
    for (int mi = 0; mi < 4; mi++)
#pragma unroll
        for (int ni = 0; ni < 4; ni++)
#pragma unroll
            for (int r = 0; r < 4; r++) acc[mi][ni][r] = 0.f;

    auto load_stage = [&](int kt, int s) {
        unsigned* base = smemU + s * 10240;
        const int k0 = kt * 32;
#pragma unroll
        for (int v = 0; v < 8; v++) {
            int cid = tid + 256 * v;
            int arr = cid >> 9;
            int r   = (cid >> 2) & 127;
            int ch  = cid & 3;
            const __nv_bfloat16* src;
            if (arr == 0)      src = Ah + (size_t)(m0 + r) * K + k0 + ch * 8;
            else if (arr == 1) src = Al + (size_t)(m0 + r) * K + k0 + ch * 8;
            else if (arr == 2) src = Wh + (size_t)(n0 + r) * K + k0 + ch * 8;
            else               src = Wl + (size_t)(n0 + r) * K + k0 + ch * 8;
            cp16(base + arr * 2560 + r * 20 + ch * 4, src);
        }
    };

    const int nk = K / 32;
    load_stage(0, 0);
    CP_COMMIT();

    for (int kt = 0; kt < nk; kt++) {
        if (kt + 1 < nk) {
            load_stage(kt + 1, (kt + 1) & 1);
            CP_COMMIT();
            CP_WAIT(1);
        } else {
            CP_WAIT(0);
        }
        __syncthreads();

        unsigned* base = smemU + (kt & 1) * 10240;
        unsigned (*As_h)[20] = (unsigned(*)[20])(base);
        unsigned (*As_l)[20] = (unsigned(*)[20])(base + 2560);
        unsigned (*Bs_h)[20] = (unsigned(*)[20])(base + 5120);
        unsigned (*Bs_l)[20] = (unsigned(*)[20])(base + 7680);

#pragma unroll
        for (int s = 0; s < 2; s++) {
            unsigned ah[4][4], al[4][4], bh[4][2], bl[4][2];
#pragma unroll
            for (int mi = 0; mi < 4; mi++) {
                int r0 = wm + 16 * mi + g, r1 = r0 + 8;
                int c0 = 8 * s + tig;
                ah[mi][0] = As_h[r0][c0];     ah[mi][1] = As_h[r1][c0];
                ah[mi][2] = As_h[r0][c0 + 4]; ah[mi][3] = As_h[r1][c0 + 4];
                al[mi][0] = As_l[r0][c0];     al[mi][1] = As_l[r1][c0];
                al[mi][2] = As_l[r0][c0 + 4]; al[mi][3] = As_l[r1][c0 + 4];
            }
#pragma unroll
            for (int ni = 0; ni < 4; ni++) {
                int n = wn + 8 * ni + g;
                int c0 = 8 * s + tig;
                bh[ni][0] = Bs_h[n][c0]; bh[ni][1] = Bs_h[n][c0 + 4];
                bl[ni][0] = Bs_l[n][c0]; bl[ni][1] = Bs_l[n][c0 + 4];
            }
#pragma unroll
            for (int mi = 0; mi < 4; mi++)
#pragma unroll
                for (int ni = 0; ni < 4; ni++) {
                    mma_bf16(acc[mi][ni], ah[mi][0], ah[mi][1], ah[mi][2], ah[mi][3],
                             bh[ni][0], bh[ni][1]);
                    mma_bf16(acc[mi][ni], ah[mi][0], ah[mi][1], ah[mi][2], ah[mi][3],
                             bl[ni][0], bl[ni][1]);
                    mma_bf16(acc[mi][ni], al[mi][0], al[mi][1], al[mi][2], al[mi][3],
                             bh[ni][0], bh[ni][1]);
                }
        }
        __syncthreads();
    }

    float2 bv[4];
#pragma unroll
    for (int ni = 0; ni < 4; ni++)
        bv[ni] = *(const float2*)(bias + n0 + wn + 8 * ni + 2 * tig);

    if (MODE == 0) {
        float cs[4][2], cq[4][2];
#pragma unroll
        for (int ni = 0; ni < 4; ni++) { cs[ni][0] = cs[ni][1] = 0.f; cq[ni][0] = cq[ni][1] = 0.f; }
#pragma unroll
        for (int mi = 0; mi < 4; mi++) {
            int r0 = m0 + wm + 16 * mi + g, r1 = r0 + 8;
#pragma unroll
            for (int ni = 0; ni < 4; ni++) {
                int n = n0 + wn + 8 * ni + 2 * tig;
                float v0 = acc[mi][ni][0] + bv[ni].x;
                float v1 = acc[mi][ni][1] + bv[ni].y;
                float v2 = acc[mi][ni][2] + bv[ni].x;
                float v3 = acc[mi][ni][3] + bv[ni].y;
                v0 = v0 > 0.f ? v0 : 0.2f * v0;
                v1 = v1 > 0.f ? v1 : 0.2f * v1;
                v2 = v2 > 0.f ? v2 : 0.2f * v2;
                v3 = v3 > 0.f ? v3 : 0.2f * v3;
                *(float2*)(Y + (size_t)r0 * N + n) = make_float2(v0, v1);
                *(float2*)(Y + (size_t)r1 * N + n) = make_float2(v2, v3);
                cs[ni][0] += v0 + v2; cs[ni][1] += v1 + v3;
                cq[ni][0] += v0 * v0 + v2 * v2; cq[ni][1] += v1 * v1 + v3 * v3;
            }
        }
#pragma unroll
        for (int ni = 0; ni < 4; ni++) {
            int n = wn + 8 * ni + 2 * tig;
            atomicAdd(&sSum[n],     cs[ni][0]);
            atomicAdd(&sSum[n + 1], cs[ni][1]);
            atomicAdd(&sSq[n],      cq[ni][0]);
            atomicAdd(&sSq[n + 1],  cq[ni][1]);
        }
        __syncthreads();
        if (tid < 128) {
            atomicAdd(&sums[n0 + tid],     sSum[tid]);
            atomicAdd(&sums[N + n0 + tid], sSq[tid]);
        }
    } else {
#pragma unroll
        for (int mi = 0; mi < 4; mi++) {
            int r0 = m0 + wm + 16 * mi + g, r1 = r0 + 8;
            int b0i = r0 / spatial, p0 = r0 % spatial;
            int b1i = r1 / spatial, p1 = r1 % spatial;
#pragma unroll
            for (int ni = 0; ni < 4; ni++) {
                int n = n0 + wn + 8 * ni + 2 * tig;
                float v0 = acc[mi][ni][0] + bv[ni].x;
                float v1 = acc[mi][ni][1] + bv[ni].y;
                float v2 = acc[mi][ni][2] + bv[ni].x;
                float v3 = acc[mi][ni][3] + bv[ni].y;
                v0 = 1.f / (1.f + expf(-v0));
                v1 = 1.f / (1.f + expf(-v1));
                v2 = 1.f / (1.f + expf(-v2));
                v3 = 1.f / (1.f + expf(-v3));
                Y[((size_t)b0i * N + n)     * spatial + p0] = v0;
                Y[((size_t)b0i * N + n + 1) * spatial + p0] = v1;
                Y[((size_t)b1i * N + n)     * spatial + p1] = v2;
                Y[((size_t)b1i * N + n + 1) * spatial + p1] = v3;
            }
        }
    }
}

__global__ void write_label_kernel(const int* __restrict__ label, float* __restrict__ out, int n)
{
    int i = threadIdx.x;
    if (i < n) out[i] = (float)label[i];
}

// ---------------- launcher ---------------------------------------------------
extern "C" void kernel_launch(void* const* d_in, const int* in_sizes, int n_in,
                              void* d_out, int out_size)
{
    const float* input = (const float*)d_in[0];
    const int*   label = (const int*)d_in[1];
    const float* emb   = (const float*)d_in[2];
    const float* lw[5] = {(const float*)d_in[3], (const float*)d_in[5], (const float*)d_in[7],
                          (const float*)d_in[9], (const float*)d_in[11]};
    const float* lb[5] = {(const float*)d_in[4], (const float*)d_in[6], (const float*)d_in[8],
                          (const float*)d_in[10], (const float*)d_in[12]};
    const float* cmw[5] = {(const float*)d_in[13], (const float*)d_in[15], (const float*)d_in[17],
                           (const float*)d_in[19], (const float*)d_in[21]};
    const float* cmb[5] = {(const float*)d_in[14], (const float*)d_in[16], (const float*)d_in[18],
                           (const float*)d_in[20], (const float*)d_in[22]};
    const float* bng[4] = {(const float*)d_in[23], (const float*)d_in[25],
                           (const float*)d_in[27], (const float*)d_in[29]};
    const float* bnb[4] = {(const float*)d_in[24], (const float*)d_in[26],
                           (const float*)d_in[28], (const float*)d_in[30]};

    float *pA, *pB, *pK, *pSums;
    __nv_bfloat16 *pDwH, *pDwL, *pWH, *pWL;
    cudaGetSymbolAddress((void**)&pA,    g_bufA);
    cudaGetSymbolAddress((void**)&pB,    g_bufB);
    cudaGetSymbolAddress((void**)&pDwH,  g_dwH);
    cudaGetSymbolAddress((void**)&pDwL,  g_dwL);
    cudaGetSymbolAddress((void**)&pWH,   g_wspH);
    cudaGetSymbolAddress((void**)&pWL,   g_wspL);
    cudaGetSymbolAddress((void**)&pK,    g_kern);
    cudaGetSymbolAddress((void**)&pSums, g_sums);

    float* out = (float*)d_out;

    const int SMEM = 81920;
    cudaFuncSetAttribute(mix_mma3_kernel<0>, cudaFuncAttributeMaxDynamicSharedMemorySize, SMEM);
    cudaFuncSetAttribute(mix_mma3_kernel<1>, cudaFuncAttributeMaxDynamicSharedMemorySize, SMEM);

    // ---------- prep: dyn kernels + zero sums; split mixer weights ----------
    prep_kernel<<<dim3(33, 128), 256>>>(label, emb, lw[0], lb[0], lw[1], lb[1],
                                        lw[2], lb[2], lw[3], lb[3], lw[4], lb[4],
                                        pK, pSums);
    wsplit_kernel<<<1696, 256>>>(cmw[1], cmw[2], cmw[3], cmw[4], pWH, pWL);

    // ---------- Layer 1 (fused): dwconv(3ch,128->64) + mix(3->64) ----------
    l1_fused_kernel<<<dim3(64, 128), 256>>>(input, pK + KOFF1, cmw[0], cmb[0], pA, pSums + SOFF1);

    // ---------- Layer 2 ----------
    {
        dwconv_v4_kernel<4, 64, 64, 64, 32, 32, 2, 1><<<dim3(16, 128), 16 * 16>>>(
            pA, pSums + SOFF1, bng[0], bnb[0], 1.f / (float)(128 * 64 * 64), pK + KOFF2, pDwH, pDwL);
        int M = 128 * 32 * 32, N = 128, K = 64;
        mix_mma3_kernel<0><<<dim3(M / 128, N / 128), 256, SMEM>>>(
            pDwH, pDwL, pWH + W2OFF, pWL + W2OFF, cmb[1], pB, pSums + SOFF2, M, N, K, 0);
    }
    // ---------- Layer 3 ----------
    {
        dwconv_v4_kernel<3, 128, 32, 32, 16, 16, 2, 1><<<dim3(8, 128), 32 * 8>>>(
            pB, pSums + SOFF2, bng[1], bnb[1], 1.f / (float)(128 * 32 * 32), pK + KOFF3, pDwH, pDwL);
        int M = 128 * 16 * 16, N = 256, K = 128;
        mix_mma3_kernel<0><<<dim3(M / 128, N / 128), 256, SMEM>>>(
            pDwH, pDwL, pWH + W3OFF, pWL + W3OFF, cmb[2], pA, pSums + SOFF3, M, N, K, 0);
    }
    // ---------- Layer 4 ----------
    {
        dwconv_v4_kernel<4, 256, 16, 16, 8, 8, 2, 1><<<dim3(4, 128), 64 * 4>>>(
            pA, pSums + SOFF3, bng[2], bnb[2], 1.f / (float)(128 * 16 * 16), pK + KOFF4, pDwH, pDwL);
        int M = 128 * 8 * 8, N = 512, K = 256;
        mix_mma3_kernel<0><<<dim3(M / 128, N / 128), 256, SMEM>>>(
            pDwH, pDwL, pWH + W4OFF, pWL + W4OFF, cmb[3], pB, pSums + SOFF4, M, N, K, 0);
    }
    // ---------- Layer 5 ----------
    {
        dwconv_v4_kernel<2, 512, 8, 8, 7, 7, 1, 0><<<dim3(4, 128), 128 * 4>>>(
            pB, pSums + SOFF4, bng[3], bnb[3], 1.f / (float)(128 * 8 * 8), pK + KOFF5, pDwH, pDwL);
        int M = 128 * 49, N = 512, K = 512;
        mix_mma3_kernel<1><<<dim3(M / 128, N / 128), 256, SMEM>>>(
            pDwH, pDwL, pWH + W5OFF, pWL + W5OFF, cmb[4], out, nullptr, M, N, K, 49);
    }
    // ---------- label tail ----------
    {
        long long zElems = 128LL * 512 * 49;
        long long tail = (long long)out_size - zElems;
        if (tail > 0) {
            int n = tail > 128 ? 128 : (int)tail;
            write_label_kernel<<<1, 128>>>(label, out + zElems, n);
        }
    }
}

// round 8
// speedup vs baseline: 2.7855x; 1.0425x over previous
#include <cuda_runtime.h>
#include <cuda_bf16.h>
#include <cuda_fp16.h>
#include <cstddef>

// ---------------- scratch (device globals; no allocation allowed) ----------
__device__ __half g_actA[33554432];               // mix/l1 outputs fp16 (NHWC)
__device__ __half g_actB[16777216];               // mix outputs fp16 (NHWC)
__device__ __nv_bfloat16 g_dwH[8388608];          // dwconv out hi plane (M x K)
__device__ __nv_bfloat16 g_dwL[8388608];          // dwconv out lo plane
__device__ __nv_bfloat16 g_wspH[434176];          // split mixer weights hi (N x K)
__device__ __nv_bfloat16 g_wspL[434176];          // split mixer weights lo
__device__ float g_kern[1179648];                 // all 5 dyn kernel sets
__device__ float g_sums[2048];                    // per-layer sum/sumsq regions

// dyn-kernel region offsets (floats)
#define KOFF1 0
#define KOFF2 6144
#define KOFF3 137216
#define KOFF4 284672
#define KOFF5 808960
// BN sums region offsets
#define SOFF1 0
#define SOFF2 128
#define SOFF3 384
#define SOFF4 896
// split-weight region offsets (elements, N x K layout)
#define W2OFF 0
#define W3OFF 8192
#define W4OFF 40960
#define W5OFF 172032

// ---------------- helpers ----------------------------------------------------
__device__ __forceinline__ void split1(float v, __nv_bfloat16& h, __nv_bfloat16& l)
{
    h = __float2bfloat16(v);
    l = __float2bfloat16(v - __bfloat162float(h));
}

__device__ __forceinline__ void mma_bf16(float* c, unsigned a0, unsigned a1, unsigned a2,
                                         unsigned a3, unsigned b0, unsigned b1)
{
    asm volatile(
        "mma.sync.aligned.m16n8k16.row.col.f32.bf16.bf16.f32 "
        "{%0,%1,%2,%3}, {%4,%5,%6,%7}, {%8,%9}, {%0,%1,%2,%3};\n"
        : "+f"(c[0]), "+f"(c[1]), "+f"(c[2]), "+f"(c[3])
        : "r"(a0), "r"(a1), "r"(a2), "r"(a3), "r"(b0), "r"(b1));
}

__device__ __forceinline__ void cp16(void* dst, const void* src)
{
    unsigned d = (unsigned)__cvta_generic_to_shared(dst);
    asm volatile("cp.async.cg.shared.global [%0], [%1], 16;\n" :: "r"(d), "l"(src));
}
#define CP_COMMIT() asm volatile("cp.async.commit_group;\n" ::: "memory")
#define CP_WAIT(n)  asm volatile("cp.async.wait_group %0;\n" :: "n"(n) : "memory")

// ---------------- prep: all dyn kernels (tanh(e@W+b)) + zero sums -----------
__global__ void prep_kernel(const int* __restrict__ label, const float* __restrict__ emb,
                            const float* __restrict__ w1, const float* __restrict__ b1,
                            const float* __restrict__ w2, const float* __restrict__ b2,
                            const float* __restrict__ w3, const float* __restrict__ b3,
                            const float* __restrict__ w4, const float* __restrict__ b4,
                            const float* __restrict__ w5, const float* __restrict__ b5,
                            float* __restrict__ kern, float* __restrict__ sums)
{
    int b = blockIdx.y;
    int i = blockIdx.x * 256 + threadIdx.x;
    if (b == 0 && i < 1920) sums[i] = 0.f;

    const float* W; const float* bb; int ck, off, j;
    if (i < 48)            { W = w1; bb = b1; ck = 48;   off = KOFF1; j = i; }
    else if (i < 1072)     { W = w2; bb = b2; ck = 1024; off = KOFF2; j = i - 48; }
    else if (i < 2224)     { W = w3; bb = b3; ck = 1152; off = KOFF3; j = i - 1072; }
    else if (i < 6320)     { W = w4; bb = b4; ck = 4096; off = KOFF4; j = i - 2224; }
    else if (i < 8368)     { W = w5; bb = b5; ck = 2048; off = KOFF5; j = i - 6320; }
    else return;

    const float* e = emb + label[b] * 5;
    float a = bb[j];
#pragma unroll
    for (int t = 0; t < 5; t++) a += e[t] * W[t * ck + j];
    kern[off + (size_t)b * ck + j] = tanhf(a);
}

// ---------------- wsplit: mixer weights fp32 (K x N) -> bf16 hi/lo (N x K) --
__global__ void wsplit_kernel(const float* __restrict__ w2, const float* __restrict__ w3,
                              const float* __restrict__ w4, const float* __restrict__ w5,
                              __nv_bfloat16* __restrict__ wh, __nv_bfloat16* __restrict__ wl)
{
    int i = blockIdx.x * 256 + threadIdx.x;
    const float* W; int K, N, off, j;
    if (i < 8192)        { W = w2; K = 64;  N = 128; off = W2OFF; j = i; }
    else if (i < 40960)  { W = w3; K = 128; N = 256; off = W3OFF; j = i - 8192; }
    else if (i < 172032) { W = w4; K = 256; N = 512; off = W4OFF; j = i - 40960; }
    else if (i < 434176) { W = w5; K = 512; N = 512; off = W5OFF; j = i - 172032; }
    else return;
    int n = j / K, k = j % K;
    __nv_bfloat16 h, l;
    split1(W[(size_t)k * N + n], h, l);
    wh[off + j] = h;
    wl[off + j] = l;
}

// ---------------- layer 1 fused: dwconv(3ch) + mix(3->64) + lrelu + stats ---
__global__ __launch_bounds__(256) void l1_fused_kernel(
    const float* __restrict__ x, const float* __restrict__ kern,
    const float* __restrict__ W, const float* __restrict__ bias,
    __half* __restrict__ Y, float* __restrict__ sums)
{
    __shared__ float sW[3][64];
    __shared__ float sB[64];
    __shared__ float sK[3][16];
    __shared__ float sD[3][64];
    __shared__ float sSum[64], sSq[64];

    int b = blockIdx.y, oh = blockIdx.x;
    int tid = threadIdx.x;

    if (tid < 192) sW[tid / 64][tid % 64] = W[tid];
    if (tid < 64) { sB[tid] = bias[tid]; sSum[tid] = 0.f; sSq[tid] = 0.f; }
    if (tid >= 192 && tid < 240) { int q = tid - 192; sK[q / 16][q % 16] = kern[(size_t)b * 48 + q]; }
    __syncthreads();

    if (tid < 192) {
        int c = tid / 64, ow = tid % 64;
        const float* xp = x + ((size_t)b * 3 + c) * 16384;
        float a = 0.f;
#pragma unroll
        for (int kh = 0; kh < 4; kh++) {
            int ih = oh * 2 - 1 + kh;
            if ((unsigned)ih < 128u) {
#pragma unroll
                for (int kw = 0; kw < 4; kw++) {
                    int iw = ow * 2 - 1 + kw;
                    if ((unsigned)iw < 128u) a += xp[ih * 128 + iw] * sK[c][kh * 4 + kw];
                }
            }
        }
        sD[c][ow] = a;
    }
    __syncthreads();

    int tx = tid & 63, py = tid >> 6;
    float w0 = sW[0][tx], w1 = sW[1][tx], w2 = sW[2][tx], bb = sB[tx];
    float s = 0.f, q = 0.f;
#pragma unroll
    for (int pix = py; pix < 64; pix += 4) {
        float v = fmaf(sD[0][pix], w0, fmaf(sD[1][pix], w1, fmaf(sD[2][pix], w2, bb)));
        v = v > 0.f ? v : 0.2f * v;
        Y[(((size_t)b * 64 + oh) * 64 + pix) * 64 + tx] = __float2half(v);
        s += v; q += v * v;
    }
    atomicAdd(&sSum[tx], s);
    atomicAdd(&sSq[tx], q);
    __syncthreads();
    if (tid < 64) { atomicAdd(&sums[tid], sSum[tid]); atomicAdd(&sums[64 + tid], sSq[tid]); }
}

// ---------------- dwconv v4: 2x2 register blocking, fp16 in, BN fold --------
template<int KS, int C, int Hin, int Win, int Hout, int Wout, int Stride, int Pad>
__global__ __launch_bounds__((C / 4) * ((Wout + 1) / 2)) void dwconv_v4_kernel(
    const __half* __restrict__ Yin, const float* __restrict__ sums,
    const float* __restrict__ bn_g, const float* __restrict__ bn_b, float invCnt,
    const float* __restrict__ kern,
    __nv_bfloat16* __restrict__ outH, __nv_bfloat16* __restrict__ outL)
{
    constexpr int KK = KS * KS;
    constexpr int CG = C / 4;
    constexpr int W2 = (Wout + 1) / 2;
    constexpr int NT = CG * W2;
    constexpr int SPAN = KS + Stride;            // input span covering 2 outputs
    __shared__ __align__(16) float sW[KK][C];
    __shared__ __align__(16) float sSc[C], sSh[C];

    const int b = blockIdx.y, rp = blockIdx.x;
    const int tid = threadIdx.x;

    for (int c = tid; c < C; c += NT) {
        float mean = sums[c] * invCnt;
        float var  = sums[C + c] * invCnt - mean * mean;
        float sc = bn_g[c] * rsqrtf(var + 1e-5f);
        sSc[c] = sc;
        sSh[c] = bn_b[c] - mean * sc;
    }
    const float* kb = kern + (size_t)b * C * KK;
    for (int idx = tid; idx < C * KK; idx += NT) {
        int c = idx / KK, tap = idx % KK;
        sW[tap][c] = kb[idx];
    }
    __syncthreads();

    const int cg = tid % CG, wq = tid / CG;
    const int c = cg * 4;
    const int oh0 = 2 * rp, ow0 = 2 * wq;
    const int ihB = oh0 * Stride - Pad;
    const int iwB = ow0 * Stride - Pad;
    const float4 sc = *(const float4*)&sSc[c];
    const float4 sh = *(const float4*)&sSh[c];

    float4 acc[2][2];
#pragma unroll
    for (int oy = 0; oy < 2; oy++)
#pragma unroll
        for (int ox = 0; ox < 2; ox++) acc[oy][ox] = make_float4(0.f, 0.f, 0.f, 0.f);

#pragma unroll
    for (int rr = 0; rr < SPAN; rr++) {
        int ih = ihB + rr;
        if ((unsigned)ih >= (unsigned)Hin) continue;
        float4 v[SPAN];
#pragma unroll
        for (int cc = 0; cc < SPAN; cc++) {
            int iw = iwB + cc;
            if ((unsigned)iw < (unsigned)Win) {
                const __half2* p = (const __half2*)&Yin[(((size_t)b * Hin + ih) * Win + iw) * C + c];
                float2 f0 = __half22float2(p[0]);
                float2 f1 = __half22float2(p[1]);
                v[cc].x = fmaf(f0.x, sc.x, sh.x);
                v[cc].y = fmaf(f0.y, sc.y, sh.y);
                v[cc].z = fmaf(f1.x, sc.z, sh.z);
                v[cc].w = fmaf(f1.y, sc.w, sh.w);
            } else {
                v[cc] = make_float4(0.f, 0.f, 0.f, 0.f);
            }
        }
#pragma unroll
        for (int oy = 0; oy < 2; oy++) {
            int kh = rr - oy * Stride;
            if (kh < 0 || kh >= KS) continue;
#pragma unroll
            for (int kw = 0; kw < KS; kw++) {
                float4 w = *(const float4*)&sW[kh * KS + kw][c];
#pragma unroll
                for (int ox = 0; ox < 2; ox++) {
                    float4 vv = v[kw + ox * Stride];
                    acc[oy][ox].x += vv.x * w.x;
                    acc[oy][ox].y += vv.y * w.y;
                    acc[oy][ox].z += vv.z * w.z;
                    acc[oy][ox].w += vv.w * w.w;
                }
            }
        }
    }

#pragma unroll
    for (int oy = 0; oy < 2; oy++) {
        int oh = oh0 + oy;
        if (oh >= Hout) break;
#pragma unroll
        for (int ox = 0; ox < 2; ox++) {
            int ow = ow0 + ox;
            if (ow >= Wout) break;
            float4 a = acc[oy][ox];
            __nv_bfloat16 h0, h1, h2, h3, l0, l1, l2, l3;
            split1(a.x, h0, l0); split1(a.y, h1, l1);
            split1(a.z, h2, l2); split1(a.w, h3, l3);
            size_t o = (((size_t)b * Hout + oh) * Wout + ow) * C + c;
            uint2 hv, lv;
            hv.x = (unsigned)__bfloat16_as_ushort(h0) | ((unsigned)__bfloat16_as_ushort(h1) << 16);
            hv.y = (unsigned)__bfloat16_as_ushort(h2) | ((unsigned)__bfloat16_as_ushort(h3) << 16);
            lv.x = (unsigned)__bfloat16_as_ushort(l0) | ((unsigned)__bfloat16_as_ushort(l1) << 16);
            lv.y = (unsigned)__bfloat16_as_ushort(l2) | ((unsigned)__bfloat16_as_ushort(l3) << 16);
            *(uint2*)&outH[o] = hv;
            *(uint2*)&outL[o] = lv;
        }
    }
}

// ---------------- channel mixer GEMM v3: bf16x3 MMA + cp.async pipeline -----
// MODE 0: Y fp16 row-major + stats.  MODE 1: fp32 NCHW sigmoid output.
template<int MODE>
__global__ __launch_bounds__(256) void mix_mma3_kernel(
    const __nv_bfloat16* __restrict__ Ah, const __nv_bfloat16* __restrict__ Al,
    const __nv_bfloat16* __restrict__ Wh, const __nv_bfloat16* __restrict__ Wl,
    const float* __restrict__ bias, __half* __restrict__ Yh, float* __restrict__ Yf,
    float* __restrict__ sums, int M, int N, int K, int spatial)
{
    extern __shared__ unsigned smemU[];          // 2 stages x 4 arrays x 128 x 20 u32
    __shared__ float sSum[128], sSq[128];

    const int tid  = threadIdx.x;
    const int wid  = tid >> 5, lane = tid & 31;
    const int g    = lane >> 2, tig = lane & 3;
    const int wm   = (wid >> 2) * 64;
    const int wn   = (wid & 3) * 32;
    const int m0   = blockIdx.x * 128, n0 = blockIdx.y * 128;

    if (MODE == 0) {
        if (tid < 128) { sSum[tid] = 0.f; sSq[tid] = 0.f; }
    }

    float acc[4][4][4];
#pragma unroll
    for (int mi = 0; mi < 4; mi++)
#pragma unroll
        for (int ni = 0; ni < 4; ni++)
#pragma unroll
            for (int r = 0; r < 4; r++) acc[mi][ni][r] = 0.f;

    auto load_stage = [&](int kt, int s) {
        unsigned* base = smemU + s * 10240;
        const int k0 = kt * 32;
#pragma unroll
        for (int v = 0; v < 8; v++) {
            int cid = tid + 256 * v;
            int arr = cid >> 9;
            int r   = (cid >> 2) & 127;
            int ch  = cid & 3;
            const __nv_bfloat16* src;
            if (arr == 0)      src = Ah + (size_t)(m0 + r) * K + k0 + ch * 8;
            else if (arr == 1) src = Al + (size_t)(m0 + r) * K + k0 + ch * 8;
            else if (arr == 2) src = Wh + (size_t)(n0 + r) * K + k0 + ch * 8;
            else               src = Wl + (size_t)(n0 + r) * K + k0 + ch * 8;
            cp16(base + arr * 2560 + r * 20 + ch * 4, src);
        }
    };

    const int nk = K / 32;
    load_stage(0, 0);
    CP_COMMIT();

    for (int kt = 0; kt < nk; kt++) {
        if (kt + 1 < nk) {
            load_stage(kt + 1, (kt + 1) & 1);
            CP_COMMIT();
            CP_WAIT(1);
        } else {
            CP_WAIT(0);
        }
        __syncthreads();

        unsigned* base = smemU + (kt & 1) * 10240;
        unsigned (*As_h)[20] = (unsigned(*)[20])(base);
        unsigned (*As_l)[20] = (unsigned(*)[20])(base + 2560);
        unsigned (*Bs_h)[20] = (unsigned(*)[20])(base + 5120);
        unsigned (*Bs_l)[20] = (unsigned(*)[20])(base + 7680);

#pragma unroll
        for (int s = 0; s < 2; s++) {
            unsigned ah[4][4], al[4][4], bh[4][2], bl[4][2];
#pragma unroll
            for (int mi = 0; mi < 4; mi++) {
                int r0 = wm + 16 * mi + g, r1 = r0 + 8;
                int c0 = 8 * s + tig;
                ah[mi][0] = As_h[r0][c0];     ah[mi][1] = As_h[r1][c0];
                ah[mi][2] = As_h[r0][c0 + 4]; ah[mi][3] = As_h[r1][c0 + 4];
                al[mi][0] = As_l[r0][c0];     al[mi][1] = As_l[r1][c0];
                al[mi][2] = As_l[r0][c0 + 4]; al[mi][3] = As_l[r1][c0 + 4];
            }
#pragma unroll
            for (int ni = 0; ni < 4; ni++) {
                int n = wn + 8 * ni + g;
                int c0 = 8 * s + tig;
                bh[ni][0] = Bs_h[n][c0]; bh[ni][1] = Bs_h[n][c0 + 4];
                bl[ni][0] = Bs_l[n][c0]; bl[ni][1] = Bs_l[n][c0 + 4];
            }
#pragma unroll
            for (int mi = 0; mi < 4; mi++)
#pragma unroll
                for (int ni = 0; ni < 4; ni++) {
                    mma_bf16(acc[mi][ni], ah[mi][0], ah[mi][1], ah[mi][2], ah[mi][3],
                             bh[ni][0], bh[ni][1]);
                    mma_bf16(acc[mi][ni], ah[mi][0], ah[mi][1], ah[mi][2], ah[mi][3],
                             bl[ni][0], bl[ni][1]);
                    mma_bf16(acc[mi][ni], al[mi][0], al[mi][1], al[mi][2], al[mi][3],
                             bh[ni][0], bh[ni][1]);
                }
        }
        __syncthreads();
    }

    float2 bv[4];
#pragma unroll
    for (int ni = 0; ni < 4; ni++)
        bv[ni] = *(const float2*)(bias + n0 + wn + 8 * ni + 2 * tig);

    if (MODE == 0) {
        float cs[4][2], cq[4][2];
#pragma unroll
        for (int ni = 0; ni < 4; ni++) { cs[ni][0] = cs[ni][1] = 0.f; cq[ni][0] = cq[ni][1] = 0.f; }
#pragma unroll
        for (int mi = 0; mi < 4; mi++) {
            int r0 = m0 + wm + 16 * mi + g, r1 = r0 + 8;
#pragma unroll
            for (int ni = 0; ni < 4; ni++) {
                int n = n0 + wn + 8 * ni + 2 * tig;
                float v0 = acc[mi][ni][0] + bv[ni].x;
                float v1 = acc[mi][ni][1] + bv[ni].y;
                float v2 = acc[mi][ni][2] + bv[ni].x;
                float v3 = acc[mi][ni][3] + bv[ni].y;
                v0 = v0 > 0.f ? v0 : 0.2f * v0;
                v1 = v1 > 0.f ? v1 : 0.2f * v1;
                v2 = v2 > 0.f ? v2 : 0.2f * v2;
                v3 = v3 > 0.f ? v3 : 0.2f * v3;
                *(__half2*)(Yh + (size_t)r0 * N + n) = __floats2half2_rn(v0, v1);
                *(__half2*)(Yh + (size_t)r1 * N + n) = __floats2half2_rn(v2, v3);
                cs[ni][0] += v0 + v2; cs[ni][1] += v1 + v3;
                cq[ni][0] += v0 * v0 + v2 * v2; cq[ni][1] += v1 * v1 + v3 * v3;
            }
        }
#pragma unroll
        for (int ni = 0; ni < 4; ni++) {
            int n = wn + 8 * ni + 2 * tig;
            atomicAdd(&sSum[n],     cs[ni][0]);
            atomicAdd(&sSum[n + 1], cs[ni][1]);
            atomicAdd(&sSq[n],      cq[ni][0]);
            atomicAdd(&sSq[n + 1],  cq[ni][1]);
        }
        __syncthreads();
        if (tid < 128) {
            atomicAdd(&sums[n0 + tid],     sSum[tid]);
            atomicAdd(&sums[N + n0 + tid], sSq[tid]);
        }
    } else {
#pragma unroll
        for (int mi = 0; mi < 4; mi++) {
            int r0 = m0 + wm + 16 * mi + g, r1 = r0 + 8;
            int b0i = r0 / spatial, p0 = r0 % spatial;
            int b1i = r1 / spatial, p1 = r1 % spatial;
#pragma unroll
            for (int ni = 0; ni < 4; ni++) {
                int n = n0 + wn + 8 * ni + 2 * tig;
                float v0 = acc[mi][ni][0] + bv[ni].x;
                float v1 = acc[mi][ni][1] + bv[ni].y;
                float v2 = acc[mi][ni][2] + bv[ni].x;
                float v3 = acc[mi][ni][3] + bv[ni].y;
                v0 = 1.f / (1.f + expf(-v0));
                v1 = 1.f / (1.f + expf(-v1));
                v2 = 1.f / (1.f + expf(-v2));
                v3 = 1.f / (1.f + expf(-v3));
                Yf[((size_t)b0i * N + n)     * spatial + p0] = v0;
                Yf[((size_t)b0i * N + n + 1) * spatial + p0] = v1;
                Yf[((size_t)b1i * N + n)     * spatial + p1] = v2;
                Yf[((size_t)b1i * N + n + 1) * spatial + p1] = v3;
            }
        }
    }
}

__global__ void write_label_kernel(const int* __restrict__ label, float* __restrict__ out, int n)
{
    int i = threadIdx.x;
    if (i < n) out[i] = (float)label[i];
}

// ---------------- launcher ---------------------------------------------------
extern "C" void kernel_launch(void* const* d_in, const int* in_sizes, int n_in,
                              void* d_out, int out_size)
{
    const float* input = (const float*)d_in[0];
    const int*   label = (const int*)d_in[1];
    const float* emb   = (const float*)d_in[2];
    const float* lw[5] = {(const float*)d_in[3], (const float*)d_in[5], (const float*)d_in[7],
                          (const float*)d_in[9], (const float*)d_in[11]};
    const float* lb[5] = {(const float*)d_in[4], (const float*)d_in[6], (const float*)d_in[8],
                          (const float*)d_in[10], (const float*)d_in[12]};
    const float* cmw[5] = {(const float*)d_in[13], (const float*)d_in[15], (const float*)d_in[17],
                           (const float*)d_in[19], (const float*)d_in[21]};
    const float* cmb[5] = {(const float*)d_in[14], (const float*)d_in[16], (const float*)d_in[18],
                           (const float*)d_in[20], (const float*)d_in[22]};
    const float* bng[4] = {(const float*)d_in[23], (const float*)d_in[25],
                           (const float*)d_in[27], (const float*)d_in[29]};
    const float* bnb[4] = {(const float*)d_in[24], (const float*)d_in[26],
                           (const float*)d_in[28], (const float*)d_in[30]};

    float *pK, *pSums;
    __half *pA, *pB;
    __nv_bfloat16 *pDwH, *pDwL, *pWH, *pWL;
    cudaGetSymbolAddress((void**)&pA,    g_actA);
    cudaGetSymbolAddress((void**)&pB,    g_actB);
    cudaGetSymbolAddress((void**)&pDwH,  g_dwH);
    cudaGetSymbolAddress((void**)&pDwL,  g_dwL);
    cudaGetSymbolAddress((void**)&pWH,   g_wspH);
    cudaGetSymbolAddress((void**)&pWL,   g_wspL);
    cudaGetSymbolAddress((void**)&pK,    g_kern);
    cudaGetSymbolAddress((void**)&pSums, g_sums);

    float* out = (float*)d_out;

    const int SMEM = 81920;
    cudaFuncSetAttribute(mix_mma3_kernel<0>, cudaFuncAttributeMaxDynamicSharedMemorySize, SMEM);
    cudaFuncSetAttribute(mix_mma3_kernel<1>, cudaFuncAttributeMaxDynamicSharedMemorySize, SMEM);

    // ---------- prep: dyn kernels + zero sums; split mixer weights ----------
    prep_kernel<<<dim3(33, 128), 256>>>(label, emb, lw[0], lb[0], lw[1], lb[1],
                                        lw[2], lb[2], lw[3], lb[3], lw[4], lb[4],
                                        pK, pSums);
    wsplit_kernel<<<1696, 256>>>(cmw[1], cmw[2], cmw[3], cmw[4], pWH, pWL);

    // ---------- Layer 1 (fused): dwconv(3ch,128->64) + mix(3->64) ----------
    l1_fused_kernel<<<dim3(64, 128), 256>>>(input, pK + KOFF1, cmw[0], cmb[0], pA, pSums + SOFF1);

    // ---------- Layer 2 ----------
    {
        dwconv_v4_kernel<4, 64, 64, 64, 32, 32, 2, 1><<<dim3(16, 128), 16 * 16>>>(
            pA, pSums + SOFF1, bng[0], bnb[0], 1.f / (float)(128 * 64 * 64), pK + KOFF2, pDwH, pDwL);
        int M = 128 * 32 * 32, N = 128, K = 64;
        mix_mma3_kernel<0><<<dim3(M / 128, N / 128), 256, SMEM>>>(
            pDwH, pDwL, pWH + W2OFF, pWL + W2OFF, cmb[1], pB, nullptr, pSums + SOFF2, M, N, K, 0);
    }
    // ---------- Layer 3 ----------
    {
        dwconv_v4_kernel<3, 128, 32, 32, 16, 16, 2, 1><<<dim3(8, 128), 32 * 8>>>(
            pB, pSums + SOFF2, bng[1], bnb[1], 1.f / (float)(128 * 32 * 32), pK + KOFF3, pDwH, pDwL);
        int M = 128 * 16 * 16, N = 256, K = 128;
        mix_mma3_kernel<0><<<dim3(M / 128, N / 128), 256, SMEM>>>(
            pDwH, pDwL, pWH + W3OFF, pWL + W3OFF, cmb[2], pA, nullptr, pSums + SOFF3, M, N, K, 0);
    }
    // ---------- Layer 4 ----------
    {
        dwconv_v4_kernel<4, 256, 16, 16, 8, 8, 2, 1><<<dim3(4, 128), 64 * 4>>>(
            pA, pSums + SOFF3, bng[2], bnb[2], 1.f / (float)(128 * 16 * 16), pK + KOFF4, pDwH, pDwL);
        int M = 128 * 8 * 8, N = 512, K = 256;
        mix_mma3_kernel<0><<<dim3(M / 128, N / 128), 256, SMEM>>>(
            pDwH, pDwL, pWH + W4OFF, pWL + W4OFF, cmb[3], pB, nullptr, pSums + SOFF4, M, N, K, 0);
    }
    // ---------- Layer 5 ----------
    {
        dwconv_v4_kernel<2, 512, 8, 8, 7, 7, 1, 0><<<dim3(4, 128), 128 * 4>>>(
            pB, pSums + SOFF4, bng[3], bnb[3], 1.f / (float)(128 * 8 * 8), pK + KOFF5, pDwH, pDwL);
        int M = 128 * 49, N = 512, K = 512;
        mix_mma3_kernel<1><<<dim3(M / 128, N / 128), 256, SMEM>>>(
            pDwH, pDwL, pWH + W5OFF, pWL + W5OFF, cmb[4], nullptr, out, nullptr, M, N, K, 49);
    }
    // ---------- label tail ----------
    {
        long long zElems = 128LL * 512 * 49;
        long long tail = (long long)out_size - zElems;
        if (tail > 0) {
            int n = tail > 128 ? 128 : (int)tail;
            write_label_kernel<<<1, 128>>>(label, out + zElems, n);
        }
    }
}

// round 9
// speedup vs baseline: 3.7460x; 1.3448x over previous
#include <cuda_runtime.h>
#include <cuda_bf16.h>
#include <cuda_fp16.h>
#include <cstddef>

// ---------------- scratch (device globals; no allocation allowed) ----------
__device__ __half g_actA[33554432];               // mix/l1 outputs fp16 (NHWC)
__device__ __half g_actB[16777216];               // mix outputs fp16 (NHWC)
__device__ __half g_dwF[8388608];                 // dwconv out fp16 (M x K)
__device__ __half g_wspH[434176];                 // split mixer weights hi (N x K)
__device__ __half g_wspL[434176];                 // split mixer weights lo
__device__ float g_kern[1179648];                 // all 5 dyn kernel sets
__device__ float g_sums[2048];                    // per-layer sum/sumsq regions

// dyn-kernel region offsets (floats)
#define KOFF1 0
#define KOFF2 6144
#define KOFF3 137216
#define KOFF4 284672
#define KOFF5 808960
// BN sums region offsets
#define SOFF1 0
#define SOFF2 128
#define SOFF3 384
#define SOFF4 896
// split-weight region offsets (elements, N x K layout)
#define W2OFF 0
#define W3OFF 8192
#define W4OFF 40960
#define W5OFF 172032

// ---------------- helpers ----------------------------------------------------
__device__ __forceinline__ void mma_f16(float* c, unsigned a0, unsigned a1, unsigned a2,
                                        unsigned a3, unsigned b0, unsigned b1)
{
    asm volatile(
        "mma.sync.aligned.m16n8k16.row.col.f32.f16.f16.f32 "
        "{%0,%1,%2,%3}, {%4,%5,%6,%7}, {%8,%9}, {%0,%1,%2,%3};\n"
        : "+f"(c[0]), "+f"(c[1]), "+f"(c[2]), "+f"(c[3])
        : "r"(a0), "r"(a1), "r"(a2), "r"(a3), "r"(b0), "r"(b1));
}

__device__ __forceinline__ void cp16(void* dst, const void* src)
{
    unsigned d = (unsigned)__cvta_generic_to_shared(dst);
    asm volatile("cp.async.cg.shared.global [%0], [%1], 16;\n" :: "r"(d), "l"(src));
}
#define CP_COMMIT() asm volatile("cp.async.commit_group;\n" ::: "memory")
#define CP_WAIT(n)  asm volatile("cp.async.wait_group %0;\n" :: "n"(n) : "memory")

// ---------------- prep: all dyn kernels (tanh(e@W+b)) + zero sums -----------
__global__ void prep_kernel(const int* __restrict__ label, const float* __restrict__ emb,
                            const float* __restrict__ w1, const float* __restrict__ b1,
                            const float* __restrict__ w2, const float* __restrict__ b2,
                            const float* __restrict__ w3, const float* __restrict__ b3,
                            const float* __restrict__ w4, const float* __restrict__ b4,
                            const float* __restrict__ w5, const float* __restrict__ b5,
                            float* __restrict__ kern, float* __restrict__ sums)
{
    int b = blockIdx.y;
    int i = blockIdx.x * 256 + threadIdx.x;
    if (b == 0 && i < 1920) sums[i] = 0.f;

    const float* W; const float* bb; int ck, off, j;
    if (i < 48)            { W = w1; bb = b1; ck = 48;   off = KOFF1; j = i; }
    else if (i < 1072)     { W = w2; bb = b2; ck = 1024; off = KOFF2; j = i - 48; }
    else if (i < 2224)     { W = w3; bb = b3; ck = 1152; off = KOFF3; j = i - 1072; }
    else if (i < 6320)     { W = w4; bb = b4; ck = 4096; off = KOFF4; j = i - 2224; }
    else if (i < 8368)     { W = w5; bb = b5; ck = 2048; off = KOFF5; j = i - 6320; }
    else return;

    const float* e = emb + label[b] * 5;
    float a = bb[j];
#pragma unroll
    for (int t = 0; t < 5; t++) a += e[t] * W[t * ck + j];
    kern[off + (size_t)b * ck + j] = tanhf(a);
}

// ---------------- wsplit: mixer weights fp32 (K x N) -> fp16 hi/lo (N x K) --
__global__ void wsplit_kernel(const float* __restrict__ w2, const float* __restrict__ w3,
                              const float* __restrict__ w4, const float* __restrict__ w5,
                              __half* __restrict__ wh, __half* __restrict__ wl)
{
    int i = blockIdx.x * 256 + threadIdx.x;
    const float* W; int K, N, off, j;
    if (i < 8192)        { W = w2; K = 64;  N = 128; off = W2OFF; j = i; }
    else if (i < 40960)  { W = w3; K = 128; N = 256; off = W3OFF; j = i - 8192; }
    else if (i < 172032) { W = w4; K = 256; N = 512; off = W4OFF; j = i - 40960; }
    else if (i < 434176) { W = w5; K = 512; N = 512; off = W5OFF; j = i - 172032; }
    else return;
    int n = j / K, k = j % K;
    float w = W[(size_t)k * N + n];
    __half h = __float2half(w);
    __half l = __float2half(w - __half2float(h));
    wh[off + j] = h;
    wl[off + j] = l;
}

// ---------------- layer 1 fused: dwconv(3ch) + mix(3->64) + lrelu + stats ---
__global__ __launch_bounds__(256) void l1_fused_kernel(
    const float* __restrict__ x, const float* __restrict__ kern,
    const float* __restrict__ W, const float* __restrict__ bias,
    __half* __restrict__ Y, float* __restrict__ sums)
{
    __shared__ float sW[3][64];
    __shared__ float sB[64];
    __shared__ float sK[3][16];
    __shared__ float sD[3][64];
    __shared__ float sSum[64], sSq[64];

    int b = blockIdx.y, oh = blockIdx.x;
    int tid = threadIdx.x;

    if (tid < 192) sW[tid / 64][tid % 64] = W[tid];
    if (tid < 64) { sB[tid] = bias[tid]; sSum[tid] = 0.f; sSq[tid] = 0.f; }
    if (tid >= 192 && tid < 240) { int q = tid - 192; sK[q / 16][q % 16] = kern[(size_t)b * 48 + q]; }
    __syncthreads();

    if (tid < 192) {
        int c = tid / 64, ow = tid % 64;
        const float* xp = x + ((size_t)b * 3 + c) * 16384;
        float a = 0.f;
#pragma unroll
        for (int kh = 0; kh < 4; kh++) {
            int ih = oh * 2 - 1 + kh;
            if ((unsigned)ih < 128u) {
#pragma unroll
                for (int kw = 0; kw < 4; kw++) {
                    int iw = ow * 2 - 1 + kw;
                    if ((unsigned)iw < 128u) a += xp[ih * 128 + iw] * sK[c][kh * 4 + kw];
                }
            }
        }
        sD[c][ow] = a;
    }
    __syncthreads();

    int tx = tid & 63, py = tid >> 6;
    float w0 = sW[0][tx], w1 = sW[1][tx], w2 = sW[2][tx], bb = sB[tx];
    float s = 0.f, q = 0.f;
#pragma unroll
    for (int pix = py; pix < 64; pix += 4) {
        float v = fmaf(sD[0][pix], w0, fmaf(sD[1][pix], w1, fmaf(sD[2][pix], w2, bb)));
        v = v > 0.f ? v : 0.2f * v;
        Y[(((size_t)b * 64 + oh) * 64 + pix) * 64 + tx] = __float2half(v);
        s += v; q += v * v;
    }
    atomicAdd(&sSum[tx], s);
    atomicAdd(&sSq[tx], q);
    __syncthreads();
    if (tid < 64) { atomicAdd(&sums[tid], sSum[tid]); atomicAdd(&sums[64 + tid], sSq[tid]); }
}

// ---------------- dwconv v4: 2x2 register blocking, fp16 in/out, BN fold ----
template<int KS, int C, int Hin, int Win, int Hout, int Wout, int Stride, int Pad>
__global__ __launch_bounds__((C / 4) * ((Wout + 1) / 2)) void dwconv_v4_kernel(
    const __half* __restrict__ Yin, const float* __restrict__ sums,
    const float* __restrict__ bn_g, const float* __restrict__ bn_b, float invCnt,
    const float* __restrict__ kern, __half* __restrict__ outF)
{
    constexpr int KK = KS * KS;
    constexpr int CG = C / 4;
    constexpr int W2 = (Wout + 1) / 2;
    constexpr int NT = CG * W2;
    constexpr int SPAN = KS + Stride;            // input span covering 2 outputs
    __shared__ __align__(16) float sW[KK][C];
    __shared__ __align__(16) float sSc[C], sSh[C];

    const int b = blockIdx.y, rp = blockIdx.x;
    const int tid = threadIdx.x;

    for (int c = tid; c < C; c += NT) {
        float mean = sums[c] * invCnt;
        float var  = sums[C + c] * invCnt - mean * mean;
        float sc = bn_g[c] * rsqrtf(var + 1e-5f);
        sSc[c] = sc;
        sSh[c] = bn_b[c] - mean * sc;
    }
    const float* kb = kern + (size_t)b * C * KK;
    for (int idx = tid; idx < C * KK; idx += NT) {
        int c = idx / KK, tap = idx % KK;
        sW[tap][c] = kb[idx];
    }
    __syncthreads();

    const int cg = tid % CG, wq = tid / CG;
    const int c = cg * 4;
    const int oh0 = 2 * rp, ow0 = 2 * wq;
    const int ihB = oh0 * Stride - Pad;
    const int iwB = ow0 * Stride - Pad;
    const float4 sc = *(const float4*)&sSc[c];
    const float4 sh = *(const float4*)&sSh[c];

    float4 acc[2][2];
#pragma unroll
    for (int oy = 0; oy < 2; oy++)
#pragma unroll
        for (int ox = 0; ox < 2; ox++) acc[oy][ox] = make_float4(0.f, 0.f, 0.f, 0.f);

#pragma unroll
    for (int rr = 0; rr < SPAN; rr++) {
        int ih = ihB + rr;
        if ((unsigned)ih >= (unsigned)Hin) continue;
        float4 v[SPAN];
#pragma unroll
        for (int cc = 0; cc < SPAN; cc++) {
            int iw = iwB + cc;
            if ((unsigned)iw < (unsigned)Win) {
                const __half2* p = (const __half2*)&Yin[(((size_t)b * Hin + ih) * Win + iw) * C + c];
                float2 f0 = __half22float2(p[0]);
                float2 f1 = __half22float2(p[1]);
                v[cc].x = fmaf(f0.x, sc.x, sh.x);
                v[cc].y = fmaf(f0.y, sc.y, sh.y);
                v[cc].z = fmaf(f1.x, sc.z, sh.z);
                v[cc].w = fmaf(f1.y, sc.w, sh.w);
            } else {
                v[cc] = make_float4(0.f, 0.f, 0.f, 0.f);
            }
        }
#pragma unroll
        for (int oy = 0; oy < 2; oy++) {
            int kh = rr - oy * Stride;
            if (kh < 0 || kh >= KS) continue;
#pragma unroll
            for (int kw = 0; kw < KS; kw++) {
                float4 w = *(const float4*)&sW[kh * KS + kw][c];
#pragma unroll
                for (int ox = 0; ox < 2; ox++) {
                    float4 vv = v[kw + ox * Stride];
                    acc[oy][ox].x += vv.x * w.x;
                    acc[oy][ox].y += vv.y * w.y;
                    acc[oy][ox].z += vv.z * w.z;
                    acc[oy][ox].w += vv.w * w.w;
                }
            }
        }
    }

#pragma unroll
    for (int oy = 0; oy < 2; oy++) {
        int oh = oh0 + oy;
        if (oh >= Hout) break;
#pragma unroll
        for (int ox = 0; ox < 2; ox++) {
            int ow = ow0 + ox;
            if (ow >= Wout) break;
            float4 a = acc[oy][ox];
            size_t o = (((size_t)b * Hout + oh) * Wout + ow) * C + c;
            __half2 p0 = __floats2half2_rn(a.x, a.y);
            __half2 p1 = __floats2half2_rn(a.z, a.w);
            uint2 pk;
            pk.x = *(unsigned*)&p0;
            pk.y = *(unsigned*)&p1;
            *(uint2*)&outF[o] = pk;
        }
    }
}

// ---------------- channel mixer GEMM v4: fp16 MMA (A x (Wh+Wl)), cp.async ---
// A: M x K fp16 row-major. Wh/Wl: N x K fp16 row-major.
// MODE 0: Y fp16 row-major + stats.  MODE 1: fp32 NCHW sigmoid output.
template<int MODE>
__global__ __launch_bounds__(256, 2) void mix_mma4_kernel(
    const __half* __restrict__ A,
    const __half* __restrict__ Wh, const __half* __restrict__ Wl,
    const float* __restrict__ bias, __half* __restrict__ Yh, float* __restrict__ Yf,
    float* __restrict__ sums, int M, int N, int K, int spatial)
{
    extern __shared__ unsigned smemU[];          // 2 stages x 3 arrays x 128 x 20 u32
    __shared__ float sSum[128], sSq[128];

    const int tid  = threadIdx.x;
    const int wid  = tid >> 5, lane = tid & 31;
    const int g    = lane >> 2, tig = lane & 3;
    const int wm   = (wid >> 2) * 64;
    const int wn   = (wid & 3) * 32;
    const int m0   = blockIdx.x * 128, n0 = blockIdx.y * 128;

    if (MODE == 0) {
        if (tid < 128) { sSum[tid] = 0.f; sSq[tid] = 0.f; }
    }

    float acc[4][4][4];
#pragma unroll
    for (int mi = 0; mi < 4; mi++)
#pragma unroll
        for (int ni = 0; ni < 4; ni++)
#pragma unroll
            for (int r = 0; r < 4; r++) acc[mi][ni][r] = 0.f;

    auto load_stage = [&](int kt, int s) {
        unsigned* base = smemU + s * 7680;
        const int k0 = kt * 32;
#pragma unroll
        for (int v = 0; v < 6; v++) {
            int cid = tid + 256 * v;
            int arr = cid >> 9;                  // 0:A 1:Wh 2:Wl (constant per v)
            int r   = (cid >> 2) & 127;
            int ch  = cid & 3;
            const __half* src;
            if (arr == 0)      src = A  + (size_t)(m0 + r) * K + k0 + ch * 8;
            else if (arr == 1) src = Wh + (size_t)(n0 + r) * K + k0 + ch * 8;
            else               src = Wl + (size_t)(n0 + r) * K + k0 + ch * 8;
            cp16(base + arr * 2560 + r * 20 + ch * 4, src);
        }
    };

    const int nk = K / 32;
    load_stage(0, 0);
    CP_COMMIT();

    for (int kt = 0; kt < nk; kt++) {
        if (kt + 1 < nk) {
            load_stage(kt + 1, (kt + 1) & 1);
            CP_COMMIT();
            CP_WAIT(1);
        } else {
            CP_WAIT(0);
        }
        __syncthreads();

        unsigned* base = smemU + (kt & 1) * 7680;
        unsigned (*As_)[20] = (unsigned(*)[20])(base);
        unsigned (*Bh_)[20] = (unsigned(*)[20])(base + 2560);
        unsigned (*Bl_)[20] = (unsigned(*)[20])(base + 5120);

#pragma unroll
        for (int s = 0; s < 2; s++) {
            unsigned ah[4][4], bh[4][2], bl[4][2];
#pragma unroll
            for (int mi = 0; mi < 4; mi++) {
                int r0 = wm + 16 * mi + g, r1 = r0 + 8;
                int c0 = 8 * s + tig;
                ah[mi][0] = As_[r0][c0];     ah[mi][1] = As_[r1][c0];
                ah[mi][2] = As_[r0][c0 + 4]; ah[mi][3] = As_[r1][c0 + 4];
            }
#pragma unroll
            for (int ni = 0; ni < 4; ni++) {
                int n = wn + 8 * ni + g;
                int c0 = 8 * s + tig;
                bh[ni][0] = Bh_[n][c0]; bh[ni][1] = Bh_[n][c0 + 4];
                bl[ni][0] = Bl_[n][c0]; bl[ni][1] = Bl_[n][c0 + 4];
            }
#pragma unroll
            for (int mi = 0; mi < 4; mi++)
#pragma unroll
                for (int ni = 0; ni < 4; ni++) {
                    mma_f16(acc[mi][ni], ah[mi][0], ah[mi][1], ah[mi][2], ah[mi][3],
                            bh[ni][0], bh[ni][1]);
                    mma_f16(acc[mi][ni], ah[mi][0], ah[mi][1], ah[mi][2], ah[mi][3],
                            bl[ni][0], bl[ni][1]);
                }
        }
        __syncthreads();
    }

    float2 bv[4];
#pragma unroll
    for (int ni = 0; ni < 4; ni++)
        bv[ni] = *(const float2*)(bias + n0 + wn + 8 * ni + 2 * tig);

    if (MODE == 0) {
        float cs[4][2], cq[4][2];
#pragma unroll
        for (int ni = 0; ni < 4; ni++) { cs[ni][0] = cs[ni][1] = 0.f; cq[ni][0] = cq[ni][1] = 0.f; }
#pragma unroll
        for (int mi = 0; mi < 4; mi++) {
            int r0 = m0 + wm + 16 * mi + g, r1 = r0 + 8;
#pragma unroll
            for (int ni = 0; ni < 4; ni++) {
                int n = n0 + wn + 8 * ni + 2 * tig;
                float v0 = acc[mi][ni][0] + bv[ni].x;
                float v1 = acc[mi][ni][1] + bv[ni].y;
                float v2 = acc[mi][ni][2] + bv[ni].x;
                float v3 = acc[mi][ni][3] + bv[ni].y;
                v0 = v0 > 0.f ? v0 : 0.2f * v0;
                v1 = v1 > 0.f ? v1 : 0.2f * v1;
                v2 = v2 > 0.f ? v2 : 0.2f * v2;
                v3 = v3 > 0.f ? v3 : 0.2f * v3;
                *(__half2*)(Yh + (size_t)r0 * N + n) = __floats2half2_rn(v0, v1);
                *(__half2*)(Yh + (size_t)r1 * N + n) = __floats2half2_rn(v2, v3);
                cs[ni][0] += v0 + v2; cs[ni][1] += v1 + v3;
                cq[ni][0] += v0 * v0 + v2 * v2; cq[ni][1] += v1 * v1 + v3 * v3;
            }
        }
#pragma unroll
        for (int ni = 0; ni < 4; ni++) {
            int n = wn + 8 * ni + 2 * tig;
            atomicAdd(&sSum[n],     cs[ni][0]);
            atomicAdd(&sSum[n + 1], cs[ni][1]);
            atomicAdd(&sSq[n],      cq[ni][0]);
            atomicAdd(&sSq[n + 1],  cq[ni][1]);
        }
        __syncthreads();
        if (tid < 128) {
            atomicAdd(&sums[n0 + tid],     sSum[tid]);
            atomicAdd(&sums[N + n0 + tid], sSq[tid]);
        }
    } else {
#pragma unroll
        for (int mi = 0; mi < 4; mi++) {
            int r0 = m0 + wm + 16 * mi + g, r1 = r0 + 8;
            int b0i = r0 / spatial, p0 = r0 % spatial;
            int b1i = r1 / spatial, p1 = r1 % spatial;
#pragma unroll
            for (int ni = 0; ni < 4; ni++) {
                int n = n0 + wn + 8 * ni + 2 * tig;
                float v0 = acc[mi][ni][0] + bv[ni].x;
                float v1 = acc[mi][ni][1] + bv[ni].y;
                float v2 = acc[mi][ni][2] + bv[ni].x;
                float v3 = acc[mi][ni][3] + bv[ni].y;
                v0 = 1.f / (1.f + expf(-v0));
                v1 = 1.f / (1.f + expf(-v1));
                v2 = 1.f / (1.f + expf(-v2));
                v3 = 1.f / (1.f + expf(-v3));
                Yf[((size_t)b0i * N + n)     * spatial + p0] = v0;
                Yf[((size_t)b0i * N + n + 1) * spatial + p0] = v1;
                Yf[((size_t)b1i * N + n)     * spatial + p1] = v2;
                Yf[((size_t)b1i * N + n + 1) * spatial + p1] = v3;
            }
        }
    }
}

__global__ void write_label_kernel(const int* __restrict__ label, float* __restrict__ out, int n)
{
    int i = threadIdx.x;
    if (i < n) out[i] = (float)label[i];
}

// ---------------- launcher ---------------------------------------------------
extern "C" void kernel_launch(void* const* d_in, const int* in_sizes, int n_in,
                              void* d_out, int out_size)
{
    const float* input = (const float*)d_in[0];
    const int*   label = (const int*)d_in[1];
    const float* emb   = (const float*)d_in[2];
    const float* lw[5] = {(const float*)d_in[3], (const float*)d_in[5], (const float*)d_in[7],
                          (const float*)d_in[9], (const float*)d_in[11]};
    const float* lb[5] = {(const float*)d_in[4], (const float*)d_in[6], (const float*)d_in[8],
                          (const float*)d_in[10], (const float*)d_in[12]};
    const float* cmw[5] = {(const float*)d_in[13], (const float*)d_in[15], (const float*)d_in[17],
                           (const float*)d_in[19], (const float*)d_in[21]};
    const float* cmb[5] = {(const float*)d_in[14], (const float*)d_in[16], (const float*)d_in[18],
                           (const float*)d_in[20], (const float*)d_in[22]};
    const float* bng[4] = {(const float*)d_in[23], (const float*)d_in[25],
                           (const float*)d_in[27], (const float*)d_in[29]};
    const float* bnb[4] = {(const float*)d_in[24], (const float*)d_in[26],
                           (const float*)d_in[28], (const float*)d_in[30]};

    float *pK, *pSums;
    __half *pA, *pB, *pDwF, *pWH, *pWL;
    cudaGetSymbolAddress((void**)&pA,    g_actA);
    cudaGetSymbolAddress((void**)&pB,    g_actB);
    cudaGetSymbolAddress((void**)&pDwF,  g_dwF);
    cudaGetSymbolAddress((void**)&pWH,   g_wspH);
    cudaGetSymbolAddress((void**)&pWL,   g_wspL);
    cudaGetSymbolAddress((void**)&pK,    g_kern);
    cudaGetSymbolAddress((void**)&pSums, g_sums);

    float* out = (float*)d_out;

    const int SMEM = 61440;
    cudaFuncSetAttribute(mix_mma4_kernel<0>, cudaFuncAttributeMaxDynamicSharedMemorySize, SMEM);
    cudaFuncSetAttribute(mix_mma4_kernel<1>, cudaFuncAttributeMaxDynamicSharedMemorySize, SMEM);

    // ---------- prep: dyn kernels + zero sums; split mixer weights ----------
    prep_kernel<<<dim3(33, 128), 256>>>(label, emb, lw[0], lb[0], lw[1], lb[1],
                                        lw[2], lb[2], lw[3], lb[3], lw[4], lb[4],
                                        pK, pSums);
    wsplit_kernel<<<1696, 256>>>(cmw[1], cmw[2], cmw[3], cmw[4], pWH, pWL);

    // ---------- Layer 1 (fused): dwconv(3ch,128->64) + mix(3->64) ----------
    l1_fused_kernel<<<dim3(64, 128), 256>>>(input, pK + KOFF1, cmw[0], cmb[0], pA, pSums + SOFF1);

    // ---------- Layer 2 ----------
    {
        dwconv_v4_kernel<4, 64, 64, 64, 32, 32, 2, 1><<<dim3(16, 128), 16 * 16>>>(
            pA, pSums + SOFF1, bng[0], bnb[0], 1.f / (float)(128 * 64 * 64), pK + KOFF2, pDwF);
        int M = 128 * 32 * 32, N = 128, K = 64;
        mix_mma4_kernel<0><<<dim3(M / 128, N / 128), 256, SMEM>>>(
            pDwF, pWH + W2OFF, pWL + W2OFF, cmb[1], pB, nullptr, pSums + SOFF2, M, N, K, 0);
    }
    // ---------- Layer 3 ----------
    {
        dwconv_v4_kernel<3, 128, 32, 32, 16, 16, 2, 1><<<dim3(8, 128), 32 * 8>>>(
            pB, pSums + SOFF2, bng[1], bnb[1], 1.f / (float)(128 * 32 * 32), pK + KOFF3, pDwF);
        int M = 128 * 16 * 16, N = 256, K = 128;
        mix_mma4_kernel<0><<<dim3(M / 128, N / 128), 256, SMEM>>>(
            pDwF, pWH + W3OFF, pWL + W3OFF, cmb[2], pA, nullptr, pSums + SOFF3, M, N, K, 0);
    }
    // ---------- Layer 4 ----------
    {
        dwconv_v4_kernel<4, 256, 16, 16, 8, 8, 2, 1><<<dim3(4, 128), 64 * 4>>>(
            pA, pSums + SOFF3, bng[2], bnb[2], 1.f / (float)(128 * 16 * 16), pK + KOFF4, pDwF);
        int M = 128 * 8 * 8, N = 512, K = 256;
        mix_mma4_kernel<0><<<dim3(M / 128, N / 128), 256, SMEM>>>(
            pDwF, pWH + W4OFF, pWL + W4OFF, cmb[3], pB, nullptr, pSums + SOFF4, M, N, K, 0);
    }
    // ---------- Layer 5 ----------
    {
        dwconv_v4_kernel<2, 512, 8, 8, 7, 7, 1, 0><<<dim3(4, 128), 128 * 4>>>(
            pB, pSums + SOFF4, bng[3], bnb[3], 1.f / (float)(128 * 8 * 8), pK + KOFF5, pDwF);
        int M = 128 * 49, N = 512, K = 512;
        mix_mma4_kernel<1><<<dim3(M / 128, N / 128), 256, SMEM>>>(
            pDwF, pWH + W5OFF, pWL + W5OFF, cmb[4], nullptr, out, nullptr, M, N, K, 49);
    }
    // ---------- label tail ----------
    {
        long long zElems = 128LL * 512 * 49;
        long long tail = (long long)out_size - zElems;
        if (tail > 0) {
            int n = tail > 128 ? 128 : (int)tail;
            write_label_kernel<<<1, 128>>>(label, out + zElems, n);
        }
    }
}